// round 2
// baseline (speedup 1.0000x reference)
#include <cuda_runtime.h>
#include <cuda_bf16.h>
#include <cstddef>

// Problem constants
#define BB   2
#define NN   2048
#define DIMM 2048
#define HH   16
#define DD   128
#define DI   2048          // HEADS * DIM_HEAD
#define TDI  6144          // 3 * DI
#define QK_SCALE 0.08838834764831845f  // 128^-0.5

// Scratch: qkv [B, N, 3*DI]  and attention output [B, N, DI]
__device__ float g_qkv[(size_t)BB * NN * TDI];   // 96 MB
__device__ float g_att[(size_t)BB * NN * DI];    // 32 MB

// ---------------------------------------------------------------------------
// Tiled fp32 SGEMM: C[M,Nc] = A[M,K] @ B[K,Nc], all row-major.
// BM=BN=128, BK=16, 256 threads, 8x8 micro-tile per thread.
// mode 0: A=x (param),    C=g_qkv   (QKV projection)
// mode 1: A=g_att,        C=out     (output projection)
// ---------------------------------------------------------------------------
__global__ __launch_bounds__(256) void sgemm128(const float* __restrict__ Ap,
                                                const float* __restrict__ B,
                                                float* __restrict__ Cp,
                                                int M, int Nc, int K, int mode)
{
    const float* A = (mode == 0) ? Ap : g_att;
    float*       C = (mode == 0) ? g_qkv : Cp;

    __shared__ float As[16][132];   // As[k][m], padded
    __shared__ float Bs[16][132];   // Bs[k][n], padded

    const int tid  = threadIdx.x;
    const int row0 = blockIdx.y * 128;
    const int col0 = blockIdx.x * 128;
    const int ty   = tid >> 4;   // 0..15
    const int tx   = tid & 15;   // 0..15

    float acc[8][8];
#pragma unroll
    for (int i = 0; i < 8; i++)
#pragma unroll
        for (int j = 0; j < 8; j++) acc[i][j] = 0.f;

    for (int kt = 0; kt < K; kt += 16) {
        // Load A tile [128 rows x 16 k], transpose into As[k][m]
#pragma unroll
        for (int l = 0; l < 2; l++) {
            int fl = tid + l * 256;          // 0..511 float4 slots
            int m  = fl >> 2;                // 0..127
            int k4 = (fl & 3) * 4;           // 0,4,8,12
            float4 v = *(const float4*)(A + (size_t)(row0 + m) * K + kt + k4);
            As[k4 + 0][m] = v.x;
            As[k4 + 1][m] = v.y;
            As[k4 + 2][m] = v.z;
            As[k4 + 3][m] = v.w;
        }
        // Load B tile [16 k x 128 n] directly
#pragma unroll
        for (int l = 0; l < 2; l++) {
            int fl = tid + l * 256;
            int kr = fl >> 5;                // 0..15
            int n4 = (fl & 31) * 4;          // 0..124
            *(float4*)&Bs[kr][n4] =
                *(const float4*)(B + (size_t)(kt + kr) * Nc + col0 + n4);
        }
        __syncthreads();

#pragma unroll
        for (int k = 0; k < 16; k++) {
            float a[8], bb[8];
            *(float4*)&a[0]  = *(float4*)&As[k][ty * 8];
            *(float4*)&a[4]  = *(float4*)&As[k][ty * 8 + 4];
            *(float4*)&bb[0] = *(float4*)&Bs[k][tx * 8];
            *(float4*)&bb[4] = *(float4*)&Bs[k][tx * 8 + 4];
#pragma unroll
            for (int i = 0; i < 8; i++)
#pragma unroll
                for (int j = 0; j < 8; j++)
                    acc[i][j] += a[i] * bb[j];
        }
        __syncthreads();
    }

#pragma unroll
    for (int i = 0; i < 8; i++) {
        float* Co = C + (size_t)(row0 + ty * 8 + i) * Nc + col0 + tx * 8;
        float4 v0 = make_float4(acc[i][0], acc[i][1], acc[i][2], acc[i][3]);
        float4 v1 = make_float4(acc[i][4], acc[i][5], acc[i][6], acc[i][7]);
        *(float4*)Co       = v0;
        *(float4*)(Co + 4) = v1;
    }
}

// ---------------------------------------------------------------------------
// Flash-attention (causal) fp32.
// Grid: (N/64, B*H). Block: 128 threads. 64 query rows per block,
// loop over 64-key tiles up to (and including) the diagonal tile.
// Online softmax with per-row running max/sum; K and V share one smem buffer.
// Dynamic smem layout:
//   Qs [64*129] | KV [64*129] | Ss [64*65] | row_m[64] | row_l[64] | row_scale[64]
// ---------------------------------------------------------------------------
#define ATT_SMEM_FLOATS (64 * 129 + 64 * 129 + 64 * 65 + 3 * 64)
#define ATT_SMEM_BYTES  (ATT_SMEM_FLOATS * 4)

__global__ __launch_bounds__(128) void attn_kernel()
{
    const float* __restrict__ qkv = g_qkv;
    float* __restrict__ att = g_att;

    extern __shared__ float sm[];
    float* Qs        = sm;                    // stride 129
    float* KV        = Qs + 64 * 129;         // K: stride 129, V: stride 128
    float* Ss        = KV + 64 * 129;         // stride 65
    float* row_m     = Ss + 64 * 65;
    float* row_l     = row_m + 64;
    float* row_scale = row_l + 64;

    const int bh  = blockIdx.y;          // 0..31
    const int b   = bh >> 4;
    const int h   = bh & 15;
    const int m0  = blockIdx.x * 64;
    const int tid = threadIdx.x;
    const int tr  = tid >> 3;            // 0..15  (row group)
    const int tc  = tid & 7;             // 0..7   (col group)

    // ---- Load Q tile [64 x 128], pre-scaled ----
    const float* Qg = qkv + ((size_t)(b * NN + m0)) * TDI + h * DD;
#pragma unroll
    for (int l = 0; l < 16; l++) {
        int fl = tid + l * 128;          // 0..2047 float4 slots
        int r  = fl >> 5;                // 0..63
        int d4 = (fl & 31) * 4;          // 0..124
        float4 v = *(const float4*)(Qg + (size_t)r * TDI + d4);
        float* q = &Qs[r * 129 + d4];
        q[0] = v.x * QK_SCALE;
        q[1] = v.y * QK_SCALE;
        q[2] = v.z * QK_SCALE;
        q[3] = v.w * QK_SCALE;
    }
    if (tid < 64) { row_m[tid] = -1e30f; row_l[tid] = 0.f; }

    float o[4][16];
#pragma unroll
    for (int i = 0; i < 4; i++)
#pragma unroll
        for (int c = 0; c < 16; c++) o[i][c] = 0.f;

    const int ntiles = blockIdx.x + 1;   // causal: keys only up to diagonal
    for (int t = 0; t < ntiles; t++) {
        const int k0 = t * 64;
        __syncthreads();   // previous V reads done before overwriting KV

        // ---- Load K tile [64 x 128] into KV (stride 129) ----
        const float* Kg = qkv + ((size_t)(b * NN + k0)) * TDI + DI + h * DD;
#pragma unroll
        for (int l = 0; l < 16; l++) {
            int fl = tid + l * 128;
            int r  = fl >> 5;
            int d4 = (fl & 31) * 4;
            float4 v = *(const float4*)(Kg + (size_t)r * TDI + d4);
            float* kd = &KV[r * 129 + d4];
            kd[0] = v.x; kd[1] = v.y; kd[2] = v.z; kd[3] = v.w;
        }
        __syncthreads();

        // ---- S = Q @ K^T : thread owns rows {tr+16i}, cols {tc+8j} ----
        float acc[4][8];
#pragma unroll
        for (int i = 0; i < 4; i++)
#pragma unroll
            for (int j = 0; j < 8; j++) acc[i][j] = 0.f;

        for (int k = 0; k < 128; k++) {
            float qv[4], kv[8];
#pragma unroll
            for (int i = 0; i < 4; i++) qv[i] = Qs[(tr + 16 * i) * 129 + k];
#pragma unroll
            for (int j = 0; j < 8; j++) kv[j] = KV[(tc + 8 * j) * 129 + k];
#pragma unroll
            for (int i = 0; i < 4; i++)
#pragma unroll
                for (int j = 0; j < 8; j++)
                    acc[i][j] += qv[i] * kv[j];
        }
#pragma unroll
        for (int i = 0; i < 4; i++)
#pragma unroll
            for (int j = 0; j < 8; j++)
                Ss[(tr + 16 * i) * 65 + tc + 8 * j] = acc[i][j];
        __syncthreads();

        // ---- Softmax update (threads 0..63) in parallel with V load (64..127)
        if (tid < 64) {
            const int row = tid;
            int jlim = m0 + row - k0 + 1;     // causal: keys <= query index
            if (jlim > 64) jlim = 64;
            float mx = row_m[row];
            for (int j = 0; j < jlim; j++) mx = fmaxf(mx, Ss[row * 65 + j]);
            float sc  = __expf(row_m[row] - mx);
            float sum = 0.f;
            for (int j = 0; j < 64; j++) {
                float p = (j < jlim) ? __expf(Ss[row * 65 + j] - mx) : 0.f;
                Ss[row * 65 + j] = p;
                sum += p;
            }
            row_m[row]     = mx;
            row_l[row]     = row_l[row] * sc + sum;
            row_scale[row] = sc;
        } else {
            // Load V tile [64 x 128] into KV (stride 128, float4 direct)
            const float* Vg = qkv + ((size_t)(b * NN + k0)) * TDI + 2 * DI + h * DD;
            const int u = tid - 64;
#pragma unroll
            for (int l = 0; l < 32; l++) {
                int fl = u + l * 64;
                int r  = fl >> 5;
                int d4 = (fl & 31) * 4;
                *(float4*)&KV[r * 128 + d4] =
                    *(const float4*)(Vg + (size_t)r * TDI + d4);
            }
        }
        __syncthreads();

        // ---- O = O*scale + P @ V : thread owns rows {tr+16i}, cols tc*16..+15
        float rs[4];
#pragma unroll
        for (int i = 0; i < 4; i++) rs[i] = row_scale[tr + 16 * i];
#pragma unroll
        for (int i = 0; i < 4; i++)
#pragma unroll
            for (int c = 0; c < 16; c++) o[i][c] *= rs[i];

        for (int j = 0; j < 64; j++) {
            float p[4];
#pragma unroll
            for (int i = 0; i < 4; i++) p[i] = Ss[(tr + 16 * i) * 65 + j];
#pragma unroll
            for (int c4 = 0; c4 < 4; c4++) {
                float4 v = *(const float4*)&KV[j * 128 + tc * 16 + c4 * 4];
#pragma unroll
                for (int i = 0; i < 4; i++) {
                    o[i][c4 * 4 + 0] += p[i] * v.x;
                    o[i][c4 * 4 + 1] += p[i] * v.y;
                    o[i][c4 * 4 + 2] += p[i] * v.z;
                    o[i][c4 * 4 + 3] += p[i] * v.w;
                }
            }
        }
    }

    // ---- Epilogue: normalize and store to att[b, n, h*128 + d] ----
    float inv[4];
#pragma unroll
    for (int i = 0; i < 4; i++) inv[i] = 1.0f / row_l[tr + 16 * i];
#pragma unroll
    for (int i = 0; i < 4; i++) {
        const int row = m0 + tr + 16 * i;
        float* Og = att + ((size_t)(b * NN + row)) * DI + h * DD + tc * 16;
#pragma unroll
        for (int c4 = 0; c4 < 4; c4++) {
            float4 v = make_float4(o[i][c4 * 4 + 0] * inv[i],
                                   o[i][c4 * 4 + 1] * inv[i],
                                   o[i][c4 * 4 + 2] * inv[i],
                                   o[i][c4 * 4 + 3] * inv[i]);
            *(float4*)(Og + c4 * 4) = v;
        }
    }
}

// ---------------------------------------------------------------------------
// Launch
// ---------------------------------------------------------------------------
extern "C" void kernel_launch(void* const* d_in, const int* in_sizes, int n_in,
                              void* d_out, int out_size)
{
    const float* x     = (const float*)d_in[0];   // [2, 2048, 2048]
    const float* w_qkv = (const float*)d_in[1];   // [2048, 6144]
    const float* w_out = (const float*)d_in[2];   // [2048, 2048]
    float* out = (float*)d_out;                   // [2, 2048, 2048]

    cudaFuncSetAttribute(attn_kernel,
                         cudaFuncAttributeMaxDynamicSharedMemorySize,
                         ATT_SMEM_BYTES);

    // 1) QKV projection: [4096, 2048] @ [2048, 6144]  -> g_qkv
    sgemm128<<<dim3(TDI / 128, (BB * NN) / 128), 256>>>(
        x, w_qkv, nullptr, BB * NN, TDI, DIMM, 0);

    // 2) Causal flash attention: g_qkv -> g_att
    attn_kernel<<<dim3(NN / 64, BB * HH), 128, ATT_SMEM_BYTES>>>();

    // 3) Output projection: [4096, 2048] @ [2048, 2048]  g_att -> out
    sgemm128<<<dim3(DIMM / 128, (BB * NN) / 128), 256>>>(
        nullptr, w_out, out, BB * NN, DIMM, DIMM, 1);
}

// round 6
// speedup vs baseline: 1.6276x; 1.6276x over previous
#include <cuda_runtime.h>
#include <cuda_bf16.h>
#include <cstdint>
#include <cstddef>

// Problem constants
#define BB   2
#define NN   2048
#define DIMM 2048
#define HH   16
#define DD   128
#define DI   2048          // HEADS * DIM_HEAD
#define TDI  6144          // 3 * DI
#define QK_SCALE 0.08838834764831845f  // 128^-0.5

// Scratch: qkv [B, N, 3*DI]  and attention output [B, N, DI]
__device__ float g_qkv[(size_t)BB * NN * TDI];   // 96 MB
__device__ float g_att[(size_t)BB * NN * DI];    // 32 MB

// ---------------------------------------------------------------------------
// tf32 helpers
// ---------------------------------------------------------------------------
__device__ __forceinline__ uint32_t tf32r(float x) {
    uint32_t y;
    asm("cvt.rna.tf32.f32 %0, %1;" : "=r"(y) : "f"(x));   // b32 dst (ptxas reqt)
    return y;
}

__device__ __forceinline__ void mma_tf32(float c[4],
                                         const uint32_t a[4],
                                         const uint32_t b[2]) {
    asm volatile(
        "mma.sync.aligned.m16n8k8.row.col.f32.tf32.tf32.f32 "
        "{%0,%1,%2,%3}, {%4,%5,%6,%7}, {%8,%9}, {%0,%1,%2,%3};"
        : "+f"(c[0]), "+f"(c[1]), "+f"(c[2]), "+f"(c[3])
        : "r"(a[0]), "r"(a[1]), "r"(a[2]), "r"(a[3]),
          "r"(b[0]), "r"(b[1]));
}

// ---------------------------------------------------------------------------
// tf32 tensor-core GEMM: C[M,Nc] = A[M,K] @ B[K,Nc], row-major.
// Block tile 128x128, BK=32, 256 threads = 8 warps (2m x 4n), warp tile 64x32.
// mma.sync.m16n8k8: per warp 4x4 fragments per k8-step.
// Inputs rounded to tf32 (cvt.rna) on the smem store path.
// mode 0: A=param (x),  C=g_qkv     mode 1: A=g_att, C=param (out)
// ---------------------------------------------------------------------------
__global__ __launch_bounds__(256) void gemm_tf32(const float* __restrict__ Ap,
                                                 const float* __restrict__ B,
                                                 float* __restrict__ Cp,
                                                 int M, int Nc, int K, int mode)
{
    const float* A = (mode == 0) ? Ap : g_att;
    float*       C = (mode == 0) ? g_qkv : Cp;

    __shared__ uint32_t As[128][36];    // [m][k] tf32 bits, pad 4
    __shared__ uint32_t Bs[32][136];    // [k][n] tf32 bits, pad 8

    const int tid  = threadIdx.x;
    const int row0 = blockIdx.y * 128;
    const int col0 = blockIdx.x * 128;
    const int wid  = tid >> 5;
    const int lane = tid & 31;
    const int g    = lane >> 2;      // groupID 0..7
    const int tg   = lane & 3;       // threadID_in_group 0..3
    const int wm   = (wid & 1) * 64; // warp row offset in tile
    const int wn   = (wid >> 1) * 32;// warp col offset in tile

    float acc[4][4][4];
#pragma unroll
    for (int mi = 0; mi < 4; mi++)
#pragma unroll
        for (int ni = 0; ni < 4; ni++)
#pragma unroll
            for (int r = 0; r < 4; r++) acc[mi][ni][r] = 0.f;

    // Global load mapping (per 32-wide k-slab):
    // A tile 128x32: slot = tid + 256*l -> row=(tid>>3)+32*l, col4=(tid&7)*4
    // B tile  32x128: slot = tid + 256*l -> row=(tid>>5)+8*l, col4=(tid&31)*4
    const int arow = tid >> 3, acol = (tid & 7) * 4;
    const int brow = tid >> 5, bcol = (tid & 31) * 4;
    const float* Ag = A + (size_t)(row0 + arow) * K + acol;
    const float* Bg = B + (size_t)brow * Nc + col0 + bcol;

    float4 ra[4], rb[4];

#pragma unroll
    for (int l = 0; l < 4; l++) {
        ra[l] = *(const float4*)(Ag + (size_t)(32 * l) * K);
        rb[l] = *(const float4*)(Bg + (size_t)(8 * l) * Nc);
    }

    auto store_tiles = [&]() {
#pragma unroll
        for (int l = 0; l < 4; l++) {
            uint32_t* a = &As[arow + 32 * l][acol];
            a[0] = tf32r(ra[l].x); a[1] = tf32r(ra[l].y);
            a[2] = tf32r(ra[l].z); a[3] = tf32r(ra[l].w);
            uint32_t* b = &Bs[brow + 8 * l][bcol];
            b[0] = tf32r(rb[l].x); b[1] = tf32r(rb[l].y);
            b[2] = tf32r(rb[l].z); b[3] = tf32r(rb[l].w);
        }
    };

    auto compute = [&]() {
#pragma unroll
        for (int ks = 0; ks < 4; ks++) {
            const int k0 = ks * 8;
            uint32_t af[4][4], bf[4][2];
#pragma unroll
            for (int mi = 0; mi < 4; mi++) {
                const int r = wm + mi * 16;
                af[mi][0] = As[r + g    ][k0 + tg    ];
                af[mi][1] = As[r + g + 8][k0 + tg    ];
                af[mi][2] = As[r + g    ][k0 + tg + 4];
                af[mi][3] = As[r + g + 8][k0 + tg + 4];
            }
#pragma unroll
            for (int ni = 0; ni < 4; ni++) {
                const int c = wn + ni * 8;
                bf[ni][0] = Bs[k0 + tg    ][c + g];
                bf[ni][1] = Bs[k0 + tg + 4][c + g];
            }
#pragma unroll
            for (int mi = 0; mi < 4; mi++)
#pragma unroll
                for (int ni = 0; ni < 4; ni++)
                    mma_tf32(acc[mi][ni], af[mi], bf[ni]);
        }
    };

    store_tiles();
    __syncthreads();

    for (int kt = 32; kt < K; kt += 32) {
#pragma unroll
        for (int l = 0; l < 4; l++) {
            ra[l] = *(const float4*)(Ag + kt + (size_t)(32 * l) * K);
            rb[l] = *(const float4*)(Bg + (size_t)(kt + 8 * l) * Nc);
        }
        compute();
        __syncthreads();
        store_tiles();
        __syncthreads();
    }
    compute();

    // Epilogue: c0/c1 -> (row+g, col+2tg), c2/c3 -> (row+g+8, col+2tg)
#pragma unroll
    for (int mi = 0; mi < 4; mi++) {
#pragma unroll
        for (int ni = 0; ni < 4; ni++) {
            const int row = row0 + wm + mi * 16;
            const int col = col0 + wn + ni * 8 + 2 * tg;
            float2 v01 = make_float2(acc[mi][ni][0], acc[mi][ni][1]);
            float2 v23 = make_float2(acc[mi][ni][2], acc[mi][ni][3]);
            *(float2*)&C[(size_t)(row + g    ) * Nc + col] = v01;
            *(float2*)&C[(size_t)(row + g + 8) * Nc + col] = v23;
        }
    }
}

// ---------------------------------------------------------------------------
// Flash-attention (causal) fp32. (unchanged — known good at ~2.1 ms)
// Grid: (N/64, B*H). Block: 128 threads.
// ---------------------------------------------------------------------------
#define ATT_SMEM_FLOATS (64 * 129 + 64 * 129 + 64 * 65 + 3 * 64)
#define ATT_SMEM_BYTES  (ATT_SMEM_FLOATS * 4)

__global__ __launch_bounds__(128) void attn_kernel()
{
    const float* __restrict__ qkv = g_qkv;
    float* __restrict__ att = g_att;

    extern __shared__ float sm[];
    float* Qs        = sm;                    // stride 129
    float* KV        = Qs + 64 * 129;         // K: stride 129, V: stride 128
    float* Ss        = KV + 64 * 129;         // stride 65
    float* row_m     = Ss + 64 * 65;
    float* row_l     = row_m + 64;
    float* row_scale = row_l + 64;

    const int bh  = blockIdx.y;          // 0..31
    const int b   = bh >> 4;
    const int h   = bh & 15;
    const int m0  = blockIdx.x * 64;
    const int tid = threadIdx.x;
    const int tr  = tid >> 3;            // 0..15  (row group)
    const int tc  = tid & 7;             // 0..7   (col group)

    const float* Qg = qkv + ((size_t)(b * NN + m0)) * TDI + h * DD;
#pragma unroll
    for (int l = 0; l < 16; l++) {
        int fl = tid + l * 128;
        int r  = fl >> 5;
        int d4 = (fl & 31) * 4;
        float4 v = *(const float4*)(Qg + (size_t)r * TDI + d4);
        float* q = &Qs[r * 129 + d4];
        q[0] = v.x * QK_SCALE;
        q[1] = v.y * QK_SCALE;
        q[2] = v.z * QK_SCALE;
        q[3] = v.w * QK_SCALE;
    }
    if (tid < 64) { row_m[tid] = -1e30f; row_l[tid] = 0.f; }

    float o[4][16];
#pragma unroll
    for (int i = 0; i < 4; i++)
#pragma unroll
        for (int c = 0; c < 16; c++) o[i][c] = 0.f;

    const int ntiles = blockIdx.x + 1;
    for (int t = 0; t < ntiles; t++) {
        const int k0 = t * 64;
        __syncthreads();

        const float* Kg = qkv + ((size_t)(b * NN + k0)) * TDI + DI + h * DD;
#pragma unroll
        for (int l = 0; l < 16; l++) {
            int fl = tid + l * 128;
            int r  = fl >> 5;
            int d4 = (fl & 31) * 4;
            float4 v = *(const float4*)(Kg + (size_t)r * TDI + d4);
            float* kd = &KV[r * 129 + d4];
            kd[0] = v.x; kd[1] = v.y; kd[2] = v.z; kd[3] = v.w;
        }
        __syncthreads();

        float acc[4][8];
#pragma unroll
        for (int i = 0; i < 4; i++)
#pragma unroll
            for (int j = 0; j < 8; j++) acc[i][j] = 0.f;

        for (int k = 0; k < 128; k++) {
            float qv[4], kv[8];
#pragma unroll
            for (int i = 0; i < 4; i++) qv[i] = Qs[(tr + 16 * i) * 129 + k];
#pragma unroll
            for (int j = 0; j < 8; j++) kv[j] = KV[(tc + 8 * j) * 129 + k];
#pragma unroll
            for (int i = 0; i < 4; i++)
#pragma unroll
                for (int j = 0; j < 8; j++)
                    acc[i][j] += qv[i] * kv[j];
        }
#pragma unroll
        for (int i = 0; i < 4; i++)
#pragma unroll
            for (int j = 0; j < 8; j++)
                Ss[(tr + 16 * i) * 65 + tc + 8 * j] = acc[i][j];
        __syncthreads();

        if (tid < 64) {
            const int row = tid;
            int jlim = m0 + row - k0 + 1;
            if (jlim > 64) jlim = 64;
            float mx = row_m[row];
            for (int j = 0; j < jlim; j++) mx = fmaxf(mx, Ss[row * 65 + j]);
            float sc  = __expf(row_m[row] - mx);
            float sum = 0.f;
            for (int j = 0; j < 64; j++) {
                float p = (j < jlim) ? __expf(Ss[row * 65 + j] - mx) : 0.f;
                Ss[row * 65 + j] = p;
                sum += p;
            }
            row_m[row]     = mx;
            row_l[row]     = row_l[row] * sc + sum;
            row_scale[row] = sc;
        } else {
            const float* Vg = qkv + ((size_t)(b * NN + k0)) * TDI + 2 * DI + h * DD;
            const int u = tid - 64;
#pragma unroll
            for (int l = 0; l < 32; l++) {
                int fl = u + l * 64;
                int r  = fl >> 5;
                int d4 = (fl & 31) * 4;
                *(float4*)&KV[r * 128 + d4] =
                    *(const float4*)(Vg + (size_t)r * TDI + d4);
            }
        }
        __syncthreads();

        float rs[4];
#pragma unroll
        for (int i = 0; i < 4; i++) rs[i] = row_scale[tr + 16 * i];
#pragma unroll
        for (int i = 0; i < 4; i++)
#pragma unroll
            for (int c = 0; c < 16; c++) o[i][c] *= rs[i];

        for (int j = 0; j < 64; j++) {
            float p[4];
#pragma unroll
            for (int i = 0; i < 4; i++) p[i] = Ss[(tr + 16 * i) * 65 + j];
#pragma unroll
            for (int c4 = 0; c4 < 4; c4++) {
                float4 v = *(const float4*)&KV[j * 128 + tc * 16 + c4 * 4];
#pragma unroll
                for (int i = 0; i < 4; i++) {
                    o[i][c4 * 4 + 0] += p[i] * v.x;
                    o[i][c4 * 4 + 1] += p[i] * v.y;
                    o[i][c4 * 4 + 2] += p[i] * v.z;
                    o[i][c4 * 4 + 3] += p[i] * v.w;
                }
            }
        }
    }

    float inv[4];
#pragma unroll
    for (int i = 0; i < 4; i++) inv[i] = 1.0f / row_l[tr + 16 * i];
#pragma unroll
    for (int i = 0; i < 4; i++) {
        const int row = m0 + tr + 16 * i;
        float* Og = att + ((size_t)(b * NN + row)) * DI + h * DD + tc * 16;
#pragma unroll
        for (int c4 = 0; c4 < 4; c4++) {
            float4 v = make_float4(o[i][c4 * 4 + 0] * inv[i],
                                   o[i][c4 * 4 + 1] * inv[i],
                                   o[i][c4 * 4 + 2] * inv[i],
                                   o[i][c4 * 4 + 3] * inv[i]);
            *(float4*)(Og + c4 * 4) = v;
        }
    }
}

// ---------------------------------------------------------------------------
// Launch
// ---------------------------------------------------------------------------
extern "C" void kernel_launch(void* const* d_in, const int* in_sizes, int n_in,
                              void* d_out, int out_size)
{
    const float* x     = (const float*)d_in[0];   // [2, 2048, 2048]
    const float* w_qkv = (const float*)d_in[1];   // [2048, 6144]
    const float* w_out = (const float*)d_in[2];   // [2048, 2048]
    float* out = (float*)d_out;                   // [2, 2048, 2048]

    cudaFuncSetAttribute(attn_kernel,
                         cudaFuncAttributeMaxDynamicSharedMemorySize,
                         ATT_SMEM_BYTES);

    // 1) QKV projection: [4096, 2048] @ [2048, 6144]  -> g_qkv
    gemm_tf32<<<dim3(TDI / 128, (BB * NN) / 128), 256>>>(
        x, w_qkv, nullptr, BB * NN, TDI, DIMM, 0);

    // 2) Causal flash attention: g_qkv -> g_att
    attn_kernel<<<dim3(NN / 64, BB * HH), 128, ATT_SMEM_BYTES>>>();

    // 3) Output projection: [4096, 2048] @ [2048, 2048]  g_att -> out
    gemm_tf32<<<dim3(DIMM / 128, (BB * NN) / 128), 256>>>(
        nullptr, w_out, out, BB * NN, DIMM, DIMM, 1);
}

// round 7
// speedup vs baseline: 3.1423x; 1.9306x over previous
#include <cuda_runtime.h>
#include <cuda_bf16.h>
#include <cstdint>
#include <cstddef>

// Problem constants
#define BB   2
#define NN   2048
#define DIMM 2048
#define HH   16
#define DD   128
#define DI   2048          // HEADS * DIM_HEAD
#define TDI  6144          // 3 * DI
#define QK_SCALE 0.08838834764831845f  // 128^-0.5

// Scratch: qkv [B, N, 3*DI]  and attention output [B, N, DI]
__device__ float g_qkv[(size_t)BB * NN * TDI];   // 96 MB
__device__ float g_att[(size_t)BB * NN * DI];    // 32 MB

// ---------------------------------------------------------------------------
// tf32 helpers
// ---------------------------------------------------------------------------
__device__ __forceinline__ uint32_t tf32r(float x) {
    uint32_t y;
    asm("cvt.rna.tf32.f32 %0, %1;" : "=r"(y) : "f"(x));   // b32 dst
    return y;
}

__device__ __forceinline__ void mma_tf32(float c[4],
                                         const uint32_t a[4],
                                         const uint32_t b[2]) {
    asm volatile(
        "mma.sync.aligned.m16n8k8.row.col.f32.tf32.tf32.f32 "
        "{%0,%1,%2,%3}, {%4,%5,%6,%7}, {%8,%9}, {%0,%1,%2,%3};"
        : "+f"(c[0]), "+f"(c[1]), "+f"(c[2]), "+f"(c[3])
        : "r"(a[0]), "r"(a[1]), "r"(a[2]), "r"(a[3]),
          "r"(b[0]), "r"(b[1]));
}

// ---------------------------------------------------------------------------
// tf32 tensor-core GEMM (unchanged from Round 6 — passed at 117 TF/s)
// ---------------------------------------------------------------------------
__global__ __launch_bounds__(256) void gemm_tf32(const float* __restrict__ Ap,
                                                 const float* __restrict__ B,
                                                 float* __restrict__ Cp,
                                                 int M, int Nc, int K, int mode)
{
    const float* A = (mode == 0) ? Ap : g_att;
    float*       C = (mode == 0) ? g_qkv : Cp;

    __shared__ uint32_t As[128][36];
    __shared__ uint32_t Bs[32][136];

    const int tid  = threadIdx.x;
    const int row0 = blockIdx.y * 128;
    const int col0 = blockIdx.x * 128;
    const int wid  = tid >> 5;
    const int lane = tid & 31;
    const int g    = lane >> 2;
    const int tg   = lane & 3;
    const int wm   = (wid & 1) * 64;
    const int wn   = (wid >> 1) * 32;

    float acc[4][4][4];
#pragma unroll
    for (int mi = 0; mi < 4; mi++)
#pragma unroll
        for (int ni = 0; ni < 4; ni++)
#pragma unroll
            for (int r = 0; r < 4; r++) acc[mi][ni][r] = 0.f;

    const int arow = tid >> 3, acol = (tid & 7) * 4;
    const int brow = tid >> 5, bcol = (tid & 31) * 4;
    const float* Ag = A + (size_t)(row0 + arow) * K + acol;
    const float* Bg = B + (size_t)brow * Nc + col0 + bcol;

    float4 ra[4], rb[4];

#pragma unroll
    for (int l = 0; l < 4; l++) {
        ra[l] = *(const float4*)(Ag + (size_t)(32 * l) * K);
        rb[l] = *(const float4*)(Bg + (size_t)(8 * l) * Nc);
    }

    auto store_tiles = [&]() {
#pragma unroll
        for (int l = 0; l < 4; l++) {
            uint32_t* a = &As[arow + 32 * l][acol];
            a[0] = tf32r(ra[l].x); a[1] = tf32r(ra[l].y);
            a[2] = tf32r(ra[l].z); a[3] = tf32r(ra[l].w);
            uint32_t* b = &Bs[brow + 8 * l][bcol];
            b[0] = tf32r(rb[l].x); b[1] = tf32r(rb[l].y);
            b[2] = tf32r(rb[l].z); b[3] = tf32r(rb[l].w);
        }
    };

    auto compute = [&]() {
#pragma unroll
        for (int ks = 0; ks < 4; ks++) {
            const int k0 = ks * 8;
            uint32_t af[4][4], bf[4][2];
#pragma unroll
            for (int mi = 0; mi < 4; mi++) {
                const int r = wm + mi * 16;
                af[mi][0] = As[r + g    ][k0 + tg    ];
                af[mi][1] = As[r + g + 8][k0 + tg    ];
                af[mi][2] = As[r + g    ][k0 + tg + 4];
                af[mi][3] = As[r + g + 8][k0 + tg + 4];
            }
#pragma unroll
            for (int ni = 0; ni < 4; ni++) {
                const int c = wn + ni * 8;
                bf[ni][0] = Bs[k0 + tg    ][c + g];
                bf[ni][1] = Bs[k0 + tg + 4][c + g];
            }
#pragma unroll
            for (int mi = 0; mi < 4; mi++)
#pragma unroll
                for (int ni = 0; ni < 4; ni++)
                    mma_tf32(acc[mi][ni], af[mi], bf[ni]);
        }
    };

    store_tiles();
    __syncthreads();

    for (int kt = 32; kt < K; kt += 32) {
#pragma unroll
        for (int l = 0; l < 4; l++) {
            ra[l] = *(const float4*)(Ag + kt + (size_t)(32 * l) * K);
            rb[l] = *(const float4*)(Bg + (size_t)(kt + 8 * l) * Nc);
        }
        compute();
        __syncthreads();
        store_tiles();
        __syncthreads();
    }
    compute();

#pragma unroll
    for (int mi = 0; mi < 4; mi++) {
#pragma unroll
        for (int ni = 0; ni < 4; ni++) {
            const int row = row0 + wm + mi * 16;
            const int col = col0 + wn + ni * 8 + 2 * tg;
            float2 v01 = make_float2(acc[mi][ni][0], acc[mi][ni][1]);
            float2 v23 = make_float2(acc[mi][ni][2], acc[mi][ni][3]);
            *(float2*)&C[(size_t)(row + g    ) * Nc + col] = v01;
            *(float2*)&C[(size_t)(row + g + 8) * Nc + col] = v23;
        }
    }
}

// ---------------------------------------------------------------------------
// Flash attention (causal) with tf32 mma.sync.
// Grid (N/64, B*H), 128 threads = 4 warps; warp w owns query rows [16w,16w+16).
// Per 64-key tile: S = Q@K^T via MMA (K smem [j][d]); register softmax
// (shfl over the 4 lanes per row); P -> smem (tf32) as A operand; O += P@V
// via MMA (V smem [j][d] is the natural B layout).
// Smem (dynamic, uint32): Qs[64][132] | KVs[64][132] (K then V) | Ss[64][68]
// ---------------------------------------------------------------------------
#define ATT_SMEM_U32  (64 * 132 + 64 * 132 + 64 * 68)
#define ATT_SMEM_BYTES (ATT_SMEM_U32 * 4)

__global__ __launch_bounds__(128) void attn_mma()
{
    extern __shared__ uint32_t smu[];
    uint32_t* Qs  = smu;               // [64][132] tf32 bits
    uint32_t* KVs = Qs + 64 * 132;     // [64][132] tf32 bits (K, then V)
    uint32_t* Ss  = KVs + 64 * 132;    // [64][68]  tf32 bits (P)

    const int bh  = blockIdx.y;
    const int b   = bh >> 4;
    const int h   = bh & 15;
    const int m0  = blockIdx.x * 64;
    const int tid = threadIdx.x;
    const int wid = tid >> 5;
    const int lane = tid & 31;
    const int g   = lane >> 2;        // 0..7
    const int tg  = lane & 3;         // 0..3

    const int r0  = wid * 16 + g;     // local row (in 64-row block)
    const int r1  = r0 + 8;
    const int gr0 = m0 + r0;          // global query index
    const int gr1 = m0 + r1;

    // ---- Load Q [64 x 128], pre-scaled, tf32 bits ----
    const float* Qg = g_qkv + ((size_t)(b * NN + m0)) * TDI + h * DD;
#pragma unroll
    for (int l = 0; l < 16; l++) {
        int fl = tid + l * 128;       // 0..2047 float4 slots
        int r  = fl >> 5;
        int d4 = (fl & 31) * 4;
        float4 v = *(const float4*)(Qg + (size_t)r * TDI + d4);
        uint32_t* q = &Qs[r * 132 + d4];
        q[0] = tf32r(v.x * QK_SCALE);
        q[1] = tf32r(v.y * QK_SCALE);
        q[2] = tf32r(v.z * QK_SCALE);
        q[3] = tf32r(v.w * QK_SCALE);
    }

    float m_r[2] = {-1e30f, -1e30f};
    float l_r[2] = {0.f, 0.f};
    float O[16][4];
#pragma unroll
    for (int ni = 0; ni < 16; ni++)
#pragma unroll
        for (int r = 0; r < 4; r++) O[ni][r] = 0.f;

    const int ntiles = blockIdx.x + 1;
    for (int t = 0; t < ntiles; t++) {
        const int k0 = t * 64;
        __syncthreads();   // prior V/P reads complete

        // ---- Load K tile [64 keys x 128 d] into KVs[j][d] (tf32) ----
        const float* Kg = g_qkv + ((size_t)(b * NN + k0)) * TDI + DI + h * DD;
#pragma unroll
        for (int l = 0; l < 16; l++) {
            int fl = tid + l * 128;
            int r  = fl >> 5;
            int d4 = (fl & 31) * 4;
            float4 v = *(const float4*)(Kg + (size_t)r * TDI + d4);
            uint32_t* kd = &KVs[r * 132 + d4];
            kd[0] = tf32r(v.x); kd[1] = tf32r(v.y);
            kd[2] = tf32r(v.z); kd[3] = tf32r(v.w);
        }
        __syncthreads();

        // ---- S[16 x 64] = Q @ K^T ----
        float S[8][4];
#pragma unroll
        for (int ni = 0; ni < 8; ni++)
#pragma unroll
            for (int r = 0; r < 4; r++) S[ni][r] = 0.f;

#pragma unroll
        for (int ks = 0; ks < 16; ks++) {
            uint32_t a[4];
            const uint32_t* qb = &Qs[r0 * 132 + ks * 8 + tg];
            a[0] = qb[0];
            a[1] = qb[8 * 132];
            a[2] = qb[4];
            a[3] = qb[8 * 132 + 4];
#pragma unroll
            for (int ni = 0; ni < 8; ni++) {
                uint32_t bb[2];
                const uint32_t* kb = &KVs[(ni * 8 + g) * 132 + ks * 8 + tg];
                bb[0] = kb[0];
                bb[1] = kb[4];
                mma_tf32(S[ni], a, bb);
            }
        }

        // ---- Causal mask (diagonal tile only) ----
        if (t == ntiles - 1) {
#pragma unroll
            for (int ni = 0; ni < 8; ni++) {
                const int c = k0 + ni * 8 + 2 * tg;
                if (c     > gr0) S[ni][0] = -1e30f;
                if (c + 1 > gr0) S[ni][1] = -1e30f;
                if (c     > gr1) S[ni][2] = -1e30f;
                if (c + 1 > gr1) S[ni][3] = -1e30f;
            }
        }

        // ---- Register softmax (rows g and g+8) ----
        float mx0 = -1e30f, mx1 = -1e30f;
#pragma unroll
        for (int ni = 0; ni < 8; ni++) {
            mx0 = fmaxf(mx0, fmaxf(S[ni][0], S[ni][1]));
            mx1 = fmaxf(mx1, fmaxf(S[ni][2], S[ni][3]));
        }
        mx0 = fmaxf(mx0, __shfl_xor_sync(0xffffffffu, mx0, 1));
        mx0 = fmaxf(mx0, __shfl_xor_sync(0xffffffffu, mx0, 2));
        mx1 = fmaxf(mx1, __shfl_xor_sync(0xffffffffu, mx1, 1));
        mx1 = fmaxf(mx1, __shfl_xor_sync(0xffffffffu, mx1, 2));

        const float mn0 = fmaxf(m_r[0], mx0);
        const float mn1 = fmaxf(m_r[1], mx1);
        const float sc0 = __expf(m_r[0] - mn0);
        const float sc1 = __expf(m_r[1] - mn1);

        float sum0 = 0.f, sum1 = 0.f;
        uint32_t* s0 = &Ss[r0 * 68 + 2 * tg];
        uint32_t* s1 = &Ss[r1 * 68 + 2 * tg];
#pragma unroll
        for (int ni = 0; ni < 8; ni++) {
            float p00 = __expf(S[ni][0] - mn0);
            float p01 = __expf(S[ni][1] - mn0);
            float p10 = __expf(S[ni][2] - mn1);
            float p11 = __expf(S[ni][3] - mn1);
            sum0 += p00 + p01;
            sum1 += p10 + p11;
            s0[ni * 8 + 0] = tf32r(p00);
            s0[ni * 8 + 1] = tf32r(p01);
            s1[ni * 8 + 0] = tf32r(p10);
            s1[ni * 8 + 1] = tf32r(p11);
        }
        sum0 += __shfl_xor_sync(0xffffffffu, sum0, 1);
        sum0 += __shfl_xor_sync(0xffffffffu, sum0, 2);
        sum1 += __shfl_xor_sync(0xffffffffu, sum1, 1);
        sum1 += __shfl_xor_sync(0xffffffffu, sum1, 2);

        l_r[0] = l_r[0] * sc0 + sum0;  m_r[0] = mn0;
        l_r[1] = l_r[1] * sc1 + sum1;  m_r[1] = mn1;

#pragma unroll
        for (int ni = 0; ni < 16; ni++) {
            O[ni][0] *= sc0; O[ni][1] *= sc0;
            O[ni][2] *= sc1; O[ni][3] *= sc1;
        }

        __syncthreads();   // all warps done reading K before V overwrite

        // ---- Load V tile [64 keys x 128 d] into KVs[j][d] (tf32) ----
        const float* Vg = g_qkv + ((size_t)(b * NN + k0)) * TDI + 2 * DI + h * DD;
#pragma unroll
        for (int l = 0; l < 16; l++) {
            int fl = tid + l * 128;
            int r  = fl >> 5;
            int d4 = (fl & 31) * 4;
            float4 v = *(const float4*)(Vg + (size_t)r * TDI + d4);
            uint32_t* vd = &KVs[r * 132 + d4];
            vd[0] = tf32r(v.x); vd[1] = tf32r(v.y);
            vd[2] = tf32r(v.z); vd[3] = tf32r(v.w);
        }
        __syncthreads();

        // ---- O += P @ V  (P rows are warp-private in Ss) ----
#pragma unroll
        for (int ks = 0; ks < 8; ks++) {
            uint32_t a[4];
            const uint32_t* pb0 = &Ss[r0 * 68 + ks * 8 + tg];
            const uint32_t* pb1 = &Ss[r1 * 68 + ks * 8 + tg];
            a[0] = pb0[0];
            a[1] = pb1[0];
            a[2] = pb0[4];
            a[3] = pb1[4];
#pragma unroll
            for (int ni = 0; ni < 16; ni++) {
                uint32_t bb[2];
                const uint32_t* vb = &KVs[(ks * 8 + tg) * 132 + ni * 8 + g];
                bb[0] = vb[0];
                bb[1] = vb[4 * 132];
                mma_tf32(O[ni], a, bb);
            }
        }
    }

    // ---- Epilogue: normalize, store to g_att ----
    const float inv0 = 1.0f / l_r[0];
    const float inv1 = 1.0f / l_r[1];
    float* O0 = g_att + ((size_t)(b * NN + gr0)) * DI + h * DD;
    float* O1 = g_att + ((size_t)(b * NN + gr1)) * DI + h * DD;
#pragma unroll
    for (int ni = 0; ni < 16; ni++) {
        const int c = ni * 8 + 2 * tg;
        *(float2*)&O0[c] = make_float2(O[ni][0] * inv0, O[ni][1] * inv0);
        *(float2*)&O1[c] = make_float2(O[ni][2] * inv1, O[ni][3] * inv1);
    }
}

// ---------------------------------------------------------------------------
// Launch
// ---------------------------------------------------------------------------
extern "C" void kernel_launch(void* const* d_in, const int* in_sizes, int n_in,
                              void* d_out, int out_size)
{
    const float* x     = (const float*)d_in[0];   // [2, 2048, 2048]
    const float* w_qkv = (const float*)d_in[1];   // [2048, 6144]
    const float* w_out = (const float*)d_in[2];   // [2048, 2048]
    float* out = (float*)d_out;                   // [2, 2048, 2048]

    cudaFuncSetAttribute(attn_mma,
                         cudaFuncAttributeMaxDynamicSharedMemorySize,
                         ATT_SMEM_BYTES);

    // 1) QKV projection: [4096, 2048] @ [2048, 6144]  -> g_qkv
    gemm_tf32<<<dim3(TDI / 128, (BB * NN) / 128), 256>>>(
        x, w_qkv, nullptr, BB * NN, TDI, DIMM, 0);

    // 2) Causal flash attention (tf32 MMA): g_qkv -> g_att
    attn_mma<<<dim3(NN / 64, BB * HH), 128, ATT_SMEM_BYTES>>>();

    // 3) Output projection: [4096, 2048] @ [2048, 2048]  g_att -> out
    gemm_tf32<<<dim3(DIMM / 128, (BB * NN) / 128), 256>>>(
        nullptr, w_out, out, BB * NN, DIMM, DIMM, 1);
}

// round 8
// speedup vs baseline: 3.3947x; 1.0803x over previous
#include <cuda_runtime.h>
#include <cuda_bf16.h>
#include <cstdint>
#include <cstddef>

// Problem constants
#define BB   2
#define NN   2048
#define DIMM 2048
#define HH   16
#define DD   128
#define DI   2048          // HEADS * DIM_HEAD
#define TDI  6144          // 3 * DI
#define QK_SCALE 0.08838834764831845f  // 128^-0.5

// Scratch: qkv [B, N, 3*DI]  and attention output [B, N, DI]
__device__ float g_qkv[(size_t)BB * NN * TDI];   // 96 MB
__device__ float g_att[(size_t)BB * NN * DI];    // 32 MB

// ---------------------------------------------------------------------------
// tf32 helpers
// ---------------------------------------------------------------------------
__device__ __forceinline__ uint32_t tf32r(float x) {
    uint32_t y;
    asm("cvt.rna.tf32.f32 %0, %1;" : "=r"(y) : "f"(x));
    return y;
}

__device__ __forceinline__ void mma_tf32(float c[4],
                                         const uint32_t a[4],
                                         const uint32_t b[2]) {
    asm volatile(
        "mma.sync.aligned.m16n8k8.row.col.f32.tf32.tf32.f32 "
        "{%0,%1,%2,%3}, {%4,%5,%6,%7}, {%8,%9}, {%0,%1,%2,%3};"
        : "+f"(c[0]), "+f"(c[1]), "+f"(c[2]), "+f"(c[3])
        : "r"(a[0]), "r"(a[1]), "r"(a[2]), "r"(a[3]),
          "r"(b[0]), "r"(b[1]));
}

// ---------------------------------------------------------------------------
// tf32 tensor-core GEMM, double-buffered smem.
// Block tile 128x128, BK=32, 256 threads = 8 warps (2m x 4n), warp tile 64x32.
// Dynamic smem: As[2][128][36] | Bs[2][32][136] (uint32 tf32 bits) = 70 KB.
// Per K-iter: prefetch(regs) -> compute(buf) -> store(buf^1) -> one sync.
// mode 0: A=param (x), C=g_qkv    mode 1: A=g_att, C=param (out)
// ---------------------------------------------------------------------------
#define AS_STRIDE 36
#define BS_STRIDE 136
#define AS_BUF    (128 * AS_STRIDE)           // 4608 u32 per buffer
#define BS_BUF    (32 * BS_STRIDE)            // 4352 u32 per buffer
#define GEMM_SMEM_U32   (2 * AS_BUF + 2 * BS_BUF)
#define GEMM_SMEM_BYTES (GEMM_SMEM_U32 * 4)   // 71680 B

__global__ __launch_bounds__(256) void gemm_tf32(const float* __restrict__ Ap,
                                                 const float* __restrict__ B,
                                                 float* __restrict__ Cp,
                                                 int M, int Nc, int K, int mode)
{
    const float* A = (mode == 0) ? Ap : g_att;
    float*       C = (mode == 0) ? g_qkv : Cp;

    extern __shared__ uint32_t dsm[];
    uint32_t* AsB = dsm;                 // 2 x [128][36]
    uint32_t* BsB = dsm + 2 * AS_BUF;    // 2 x [32][136]

    const int tid  = threadIdx.x;
    const int row0 = blockIdx.y * 128;
    const int col0 = blockIdx.x * 128;
    const int wid  = tid >> 5;
    const int lane = tid & 31;
    const int g    = lane >> 2;
    const int tg   = lane & 3;
    const int wm   = (wid & 1) * 64;
    const int wn   = (wid >> 1) * 32;

    float acc[4][4][4];
#pragma unroll
    for (int mi = 0; mi < 4; mi++)
#pragma unroll
        for (int ni = 0; ni < 4; ni++)
#pragma unroll
            for (int r = 0; r < 4; r++) acc[mi][ni][r] = 0.f;

    const int arow = tid >> 3, acol = (tid & 7) * 4;
    const int brow = tid >> 5, bcol = (tid & 31) * 4;
    const float* Ag = A + (size_t)(row0 + arow) * K + acol;
    const float* Bg = B + (size_t)brow * Nc + col0 + bcol;

    float4 ra[4], rb[4];

    auto load_regs = [&](int kt) {
#pragma unroll
        for (int l = 0; l < 4; l++) {
            ra[l] = *(const float4*)(Ag + kt + (size_t)(32 * l) * K);
            rb[l] = *(const float4*)(Bg + (size_t)(kt + 8 * l) * Nc);
        }
    };

    auto store_tiles = [&](int buf) {
        uint32_t* As = AsB + buf * AS_BUF;
        uint32_t* Bs = BsB + buf * BS_BUF;
#pragma unroll
        for (int l = 0; l < 4; l++) {
            uint32_t* a = &As[(arow + 32 * l) * AS_STRIDE + acol];
            a[0] = tf32r(ra[l].x); a[1] = tf32r(ra[l].y);
            a[2] = tf32r(ra[l].z); a[3] = tf32r(ra[l].w);
            uint32_t* b = &Bs[(brow + 8 * l) * BS_STRIDE + bcol];
            b[0] = tf32r(rb[l].x); b[1] = tf32r(rb[l].y);
            b[2] = tf32r(rb[l].z); b[3] = tf32r(rb[l].w);
        }
    };

    auto compute = [&](int buf) {
        uint32_t* As = AsB + buf * AS_BUF;
        uint32_t* Bs = BsB + buf * BS_BUF;
#pragma unroll
        for (int ks = 0; ks < 4; ks++) {
            const int k0 = ks * 8;
            uint32_t af[4][4], bf[4][2];
#pragma unroll
            for (int mi = 0; mi < 4; mi++) {
                const int r = wm + mi * 16;
                af[mi][0] = As[(r + g    ) * AS_STRIDE + k0 + tg    ];
                af[mi][1] = As[(r + g + 8) * AS_STRIDE + k0 + tg    ];
                af[mi][2] = As[(r + g    ) * AS_STRIDE + k0 + tg + 4];
                af[mi][3] = As[(r + g + 8) * AS_STRIDE + k0 + tg + 4];
            }
#pragma unroll
            for (int ni = 0; ni < 4; ni++) {
                const int c = wn + ni * 8;
                bf[ni][0] = Bs[(k0 + tg    ) * BS_STRIDE + c + g];
                bf[ni][1] = Bs[(k0 + tg + 4) * BS_STRIDE + c + g];
            }
#pragma unroll
            for (int mi = 0; mi < 4; mi++)
#pragma unroll
                for (int ni = 0; ni < 4; ni++)
                    mma_tf32(acc[mi][ni], af[mi], bf[ni]);
        }
    };

    // Prologue: fill buffer 0
    load_regs(0);
    store_tiles(0);
    __syncthreads();

    int buf = 0;
    for (int kt = 0; kt < K; kt += 32) {
        const bool more = (kt + 32 < K);
        if (more) load_regs(kt + 32);
        compute(buf);
        if (more) {
            store_tiles(buf ^ 1);
            __syncthreads();
        }
        buf ^= 1;
    }

    // Epilogue
#pragma unroll
    for (int mi = 0; mi < 4; mi++) {
#pragma unroll
        for (int ni = 0; ni < 4; ni++) {
            const int row = row0 + wm + mi * 16;
            const int col = col0 + wn + ni * 8 + 2 * tg;
            float2 v01 = make_float2(acc[mi][ni][0], acc[mi][ni][1]);
            float2 v23 = make_float2(acc[mi][ni][2], acc[mi][ni][3]);
            *(float2*)&C[(size_t)(row + g    ) * Nc + col] = v01;
            *(float2*)&C[(size_t)(row + g + 8) * Nc + col] = v23;
        }
    }
}

// ---------------------------------------------------------------------------
// Flash attention (causal) with tf32 mma.sync. (unchanged — ~540 us)
// Grid (N/64, B*H), 128 threads = 4 warps.
// ---------------------------------------------------------------------------
#define ATT_SMEM_U32  (64 * 132 + 64 * 132 + 64 * 68)
#define ATT_SMEM_BYTES (ATT_SMEM_U32 * 4)

__global__ __launch_bounds__(128) void attn_mma()
{
    extern __shared__ uint32_t smu[];
    uint32_t* Qs  = smu;               // [64][132] tf32 bits
    uint32_t* KVs = Qs + 64 * 132;     // [64][132] tf32 bits (K, then V)
    uint32_t* Ss  = KVs + 64 * 132;    // [64][68]  tf32 bits (P)

    const int bh  = blockIdx.y;
    const int b   = bh >> 4;
    const int h   = bh & 15;
    const int m0  = blockIdx.x * 64;
    const int tid = threadIdx.x;
    const int wid = tid >> 5;
    const int lane = tid & 31;
    const int g   = lane >> 2;
    const int tg  = lane & 3;

    const int r0  = wid * 16 + g;
    const int r1  = r0 + 8;
    const int gr0 = m0 + r0;
    const int gr1 = m0 + r1;

    const float* Qg = g_qkv + ((size_t)(b * NN + m0)) * TDI + h * DD;
#pragma unroll
    for (int l = 0; l < 16; l++) {
        int fl = tid + l * 128;
        int r  = fl >> 5;
        int d4 = (fl & 31) * 4;
        float4 v = *(const float4*)(Qg + (size_t)r * TDI + d4);
        uint32_t* q = &Qs[r * 132 + d4];
        q[0] = tf32r(v.x * QK_SCALE);
        q[1] = tf32r(v.y * QK_SCALE);
        q[2] = tf32r(v.z * QK_SCALE);
        q[3] = tf32r(v.w * QK_SCALE);
    }

    float m_r[2] = {-1e30f, -1e30f};
    float l_r[2] = {0.f, 0.f};
    float O[16][4];
#pragma unroll
    for (int ni = 0; ni < 16; ni++)
#pragma unroll
        for (int r = 0; r < 4; r++) O[ni][r] = 0.f;

    const int ntiles = blockIdx.x + 1;
    for (int t = 0; t < ntiles; t++) {
        const int k0 = t * 64;
        __syncthreads();

        const float* Kg = g_qkv + ((size_t)(b * NN + k0)) * TDI + DI + h * DD;
#pragma unroll
        for (int l = 0; l < 16; l++) {
            int fl = tid + l * 128;
            int r  = fl >> 5;
            int d4 = (fl & 31) * 4;
            float4 v = *(const float4*)(Kg + (size_t)r * TDI + d4);
            uint32_t* kd = &KVs[r * 132 + d4];
            kd[0] = tf32r(v.x); kd[1] = tf32r(v.y);
            kd[2] = tf32r(v.z); kd[3] = tf32r(v.w);
        }
        __syncthreads();

        float S[8][4];
#pragma unroll
        for (int ni = 0; ni < 8; ni++)
#pragma unroll
            for (int r = 0; r < 4; r++) S[ni][r] = 0.f;

#pragma unroll
        for (int ks = 0; ks < 16; ks++) {
            uint32_t a[4];
            const uint32_t* qb = &Qs[r0 * 132 + ks * 8 + tg];
            a[0] = qb[0];
            a[1] = qb[8 * 132];
            a[2] = qb[4];
            a[3] = qb[8 * 132 + 4];
#pragma unroll
            for (int ni = 0; ni < 8; ni++) {
                uint32_t bb[2];
                const uint32_t* kb = &KVs[(ni * 8 + g) * 132 + ks * 8 + tg];
                bb[0] = kb[0];
                bb[1] = kb[4];
                mma_tf32(S[ni], a, bb);
            }
        }

        if (t == ntiles - 1) {
#pragma unroll
            for (int ni = 0; ni < 8; ni++) {
                const int c = k0 + ni * 8 + 2 * tg;
                if (c     > gr0) S[ni][0] = -1e30f;
                if (c + 1 > gr0) S[ni][1] = -1e30f;
                if (c     > gr1) S[ni][2] = -1e30f;
                if (c + 1 > gr1) S[ni][3] = -1e30f;
            }
        }

        float mx0 = -1e30f, mx1 = -1e30f;
#pragma unroll
        for (int ni = 0; ni < 8; ni++) {
            mx0 = fmaxf(mx0, fmaxf(S[ni][0], S[ni][1]));
            mx1 = fmaxf(mx1, fmaxf(S[ni][2], S[ni][3]));
        }
        mx0 = fmaxf(mx0, __shfl_xor_sync(0xffffffffu, mx0, 1));
        mx0 = fmaxf(mx0, __shfl_xor_sync(0xffffffffu, mx0, 2));
        mx1 = fmaxf(mx1, __shfl_xor_sync(0xffffffffu, mx1, 1));
        mx1 = fmaxf(mx1, __shfl_xor_sync(0xffffffffu, mx1, 2));

        const float mn0 = fmaxf(m_r[0], mx0);
        const float mn1 = fmaxf(m_r[1], mx1);
        const float sc0 = __expf(m_r[0] - mn0);
        const float sc1 = __expf(m_r[1] - mn1);

        float sum0 = 0.f, sum1 = 0.f;
        uint32_t* s0 = &Ss[r0 * 68 + 2 * tg];
        uint32_t* s1 = &Ss[r1 * 68 + 2 * tg];
#pragma unroll
        for (int ni = 0; ni < 8; ni++) {
            float p00 = __expf(S[ni][0] - mn0);
            float p01 = __expf(S[ni][1] - mn0);
            float p10 = __expf(S[ni][2] - mn1);
            float p11 = __expf(S[ni][3] - mn1);
            sum0 += p00 + p01;
            sum1 += p10 + p11;
            s0[ni * 8 + 0] = tf32r(p00);
            s0[ni * 8 + 1] = tf32r(p01);
            s1[ni * 8 + 0] = tf32r(p10);
            s1[ni * 8 + 1] = tf32r(p11);
        }
        sum0 += __shfl_xor_sync(0xffffffffu, sum0, 1);
        sum0 += __shfl_xor_sync(0xffffffffu, sum0, 2);
        sum1 += __shfl_xor_sync(0xffffffffu, sum1, 1);
        sum1 += __shfl_xor_sync(0xffffffffu, sum1, 2);

        l_r[0] = l_r[0] * sc0 + sum0;  m_r[0] = mn0;
        l_r[1] = l_r[1] * sc1 + sum1;  m_r[1] = mn1;

#pragma unroll
        for (int ni = 0; ni < 16; ni++) {
            O[ni][0] *= sc0; O[ni][1] *= sc0;
            O[ni][2] *= sc1; O[ni][3] *= sc1;
        }

        __syncthreads();

        const float* Vg = g_qkv + ((size_t)(b * NN + k0)) * TDI + 2 * DI + h * DD;
#pragma unroll
        for (int l = 0; l < 16; l++) {
            int fl = tid + l * 128;
            int r  = fl >> 5;
            int d4 = (fl & 31) * 4;
            float4 v = *(const float4*)(Vg + (size_t)r * TDI + d4);
            uint32_t* vd = &KVs[r * 132 + d4];
            vd[0] = tf32r(v.x); vd[1] = tf32r(v.y);
            vd[2] = tf32r(v.z); vd[3] = tf32r(v.w);
        }
        __syncthreads();

#pragma unroll
        for (int ks = 0; ks < 8; ks++) {
            uint32_t a[4];
            const uint32_t* pb0 = &Ss[r0 * 68 + ks * 8 + tg];
            const uint32_t* pb1 = &Ss[r1 * 68 + ks * 8 + tg];
            a[0] = pb0[0];
            a[1] = pb1[0];
            a[2] = pb0[4];
            a[3] = pb1[4];
#pragma unroll
            for (int ni = 0; ni < 16; ni++) {
                uint32_t bb[2];
                const uint32_t* vb = &KVs[(ks * 8 + tg) * 132 + ni * 8 + g];
                bb[0] = vb[0];
                bb[1] = vb[4 * 132];
                mma_tf32(O[ni], a, bb);
            }
        }
    }

    const float inv0 = 1.0f / l_r[0];
    const float inv1 = 1.0f / l_r[1];
    float* O0 = g_att + ((size_t)(b * NN + gr0)) * DI + h * DD;
    float* O1 = g_att + ((size_t)(b * NN + gr1)) * DI + h * DD;
#pragma unroll
    for (int ni = 0; ni < 16; ni++) {
        const int c = ni * 8 + 2 * tg;
        *(float2*)&O0[c] = make_float2(O[ni][0] * inv0, O[ni][1] * inv0);
        *(float2*)&O1[c] = make_float2(O[ni][2] * inv1, O[ni][3] * inv1);
    }
}

// ---------------------------------------------------------------------------
// Launch
// ---------------------------------------------------------------------------
extern "C" void kernel_launch(void* const* d_in, const int* in_sizes, int n_in,
                              void* d_out, int out_size)
{
    const float* x     = (const float*)d_in[0];   // [2, 2048, 2048]
    const float* w_qkv = (const float*)d_in[1];   // [2048, 6144]
    const float* w_out = (const float*)d_in[2];   // [2048, 2048]
    float* out = (float*)d_out;                   // [2, 2048, 2048]

    cudaFuncSetAttribute(gemm_tf32,
                         cudaFuncAttributeMaxDynamicSharedMemorySize,
                         GEMM_SMEM_BYTES);
    cudaFuncSetAttribute(attn_mma,
                         cudaFuncAttributeMaxDynamicSharedMemorySize,
                         ATT_SMEM_BYTES);

    // 1) QKV projection: [4096, 2048] @ [2048, 6144]  -> g_qkv
    gemm_tf32<<<dim3(TDI / 128, (BB * NN) / 128), 256, GEMM_SMEM_BYTES>>>(
        x, w_qkv, nullptr, BB * NN, TDI, DIMM, 0);

    // 2) Causal flash attention (tf32 MMA): g_qkv -> g_att
    attn_mma<<<dim3(NN / 64, BB * HH), 128, ATT_SMEM_BYTES>>>();

    // 3) Output projection: [4096, 2048] @ [2048, 2048]  g_att -> out
    gemm_tf32<<<dim3(DIMM / 128, (BB * NN) / 128), 256, GEMM_SMEM_BYTES>>>(
        nullptr, w_out, out, BB * NN, DIMM, DIMM, 1);
}

// round 9
// speedup vs baseline: 3.4937x; 1.0292x over previous
#include <cuda_runtime.h>
#include <cuda_bf16.h>
#include <cstdint>
#include <cstddef>

// Problem constants
#define BB   2
#define NN   2048
#define DIMM 2048
#define HH   16
#define DD   128
#define DI   2048          // HEADS * DIM_HEAD
#define TDI  6144          // 3 * DI
#define QK_SCALE 0.08838834764831845f  // 128^-0.5

// Scratch: qkv [B, N, 3*DI]  and attention output [B, N, DI]
__device__ float g_qkv[(size_t)BB * NN * TDI];   // 96 MB
__device__ float g_att[(size_t)BB * NN * DI];    // 32 MB

// ---------------------------------------------------------------------------
// tf32 helpers
// ---------------------------------------------------------------------------
__device__ __forceinline__ uint32_t tf32r(float x) {
    uint32_t y;
    asm("cvt.rna.tf32.f32 %0, %1;" : "=r"(y) : "f"(x));
    return y;
}

__device__ __forceinline__ void mma_tf32(float c[4],
                                         const uint32_t a[4],
                                         const uint32_t b[2]) {
    asm volatile(
        "mma.sync.aligned.m16n8k8.row.col.f32.tf32.tf32.f32 "
        "{%0,%1,%2,%3}, {%4,%5,%6,%7}, {%8,%9}, {%0,%1,%2,%3};"
        : "+f"(c[0]), "+f"(c[1]), "+f"(c[2]), "+f"(c[3])
        : "r"(a[0]), "r"(a[1]), "r"(a[2]), "r"(a[3]),
          "r"(b[0]), "r"(b[1]));
}

__device__ __forceinline__ void ldsm4(uint32_t r[4], uint32_t saddr) {
    asm volatile("ldmatrix.sync.aligned.m8n8.x4.shared.b16 {%0,%1,%2,%3}, [%4];"
        : "=r"(r[0]), "=r"(r[1]), "=r"(r[2]), "=r"(r[3]) : "r"(saddr));
}

// ---------------------------------------------------------------------------
// tf32 tensor-core GEMM, double-buffered smem + ldmatrix fragment loads.
// Block tile 128x128, BK=32, 256 threads = 8 warps (2m x 4n), warp tile 64x32.
// As: [m][k] stride 36 (u32). BsT: [n][k] stride 36 (u32, transposed store).
// A frags: ldmatrix.x4 (rows m, 32b-cols k). B frags: ldmatrix.x4 on BsT
// covers 2 n8-fragments (both k-halves) at once. 6 LDSM + 16 MMA per k8.
// mode 0: A=param (x), C=g_qkv    mode 1: A=g_att, C=param (out)
// ---------------------------------------------------------------------------
#define TS        36                     // smem row stride (u32)
#define TILE_U32  (128 * TS)             // 4608 u32 per tile buffer
#define TILE_B    (TILE_U32 * 4)         // 18432 bytes
#define GEMM_SMEM_BYTES (4 * TILE_B)     // A0 A1 B0 B1 = 73728 B

__global__ __launch_bounds__(256, 2) void gemm_tf32(const float* __restrict__ Ap,
                                                    const float* __restrict__ B,
                                                    float* __restrict__ Cp,
                                                    int M, int Nc, int K, int mode)
{
    const float* A = (mode == 0) ? Ap : g_att;
    float*       C = (mode == 0) ? g_qkv : Cp;

    extern __shared__ uint32_t dsm[];
    const uint32_t sbase = (uint32_t)__cvta_generic_to_shared(dsm);

    const int tid  = threadIdx.x;
    const int row0 = blockIdx.y * 128;
    const int col0 = blockIdx.x * 128;
    const int wid  = tid >> 5;
    const int lane = tid & 31;
    const int g    = lane >> 2;
    const int tg   = lane & 3;
    const int wm   = (wid & 1) * 64;
    const int wn   = (wid >> 1) * 32;
    const int q    = lane >> 3;      // ldmatrix quad 0..3
    const int rr   = lane & 7;       // ldmatrix row-in-matrix

    // Fragment base addresses (bytes), before buf/mi/ks offsets
    const uint32_t a_frag = sbase +
        (((wm + (q & 1) * 8 + rr) * TS + (q >> 1) * 4) << 2);
    const uint32_t b_frag = sbase + 2 * TILE_B +
        (((wn + (q >> 1) * 8 + rr) * TS + (q & 1) * 4) << 2);

    float acc[4][4][4];
#pragma unroll
    for (int mi = 0; mi < 4; mi++)
#pragma unroll
        for (int ni = 0; ni < 4; ni++)
#pragma unroll
            for (int r = 0; r < 4; r++) acc[mi][ni][r] = 0.f;

    // Global load mapping
    // A tile 128x32: float4; slot tid+256l -> row=(tid>>3)+32l, col=(tid&7)*4
    const int arow = tid >> 3, acol = (tid & 7) * 4;
    const float* Ag = A + (size_t)(row0 + arow) * K + acol;
    // B tile 32k x 128n: scalar loads down k; thread -> n=tid&127, k0=(tid>>7)*16
    const int bn = tid & 127;
    const int bk = (tid >> 7) * 16;
    const float* Bg = B + col0 + bn;

    float4 ra[4];
    float  rbv[16];

    auto load_regs = [&](int kt) {
#pragma unroll
        for (int l = 0; l < 4; l++)
            ra[l] = *(const float4*)(Ag + kt + (size_t)(32 * l) * K);
#pragma unroll
        for (int l = 0; l < 4; l++)
#pragma unroll
            for (int j = 0; j < 4; j++)
                rbv[l * 4 + j] = Bg[(size_t)(kt + bk + l * 4 + j) * Nc];
    };

    auto store_tiles = [&](int buf) {
        uint32_t* As = dsm + buf * TILE_U32;
        uint32_t* Bs = dsm + 2 * TILE_U32 + buf * TILE_U32;
#pragma unroll
        for (int l = 0; l < 4; l++) {
            uint4 av = make_uint4(tf32r(ra[l].x), tf32r(ra[l].y),
                                  tf32r(ra[l].z), tf32r(ra[l].w));
            *(uint4*)&As[(arow + 32 * l) * TS + acol] = av;
            uint4 bv = make_uint4(tf32r(rbv[l * 4 + 0]), tf32r(rbv[l * 4 + 1]),
                                  tf32r(rbv[l * 4 + 2]), tf32r(rbv[l * 4 + 3]));
            *(uint4*)&Bs[bn * TS + bk + 4 * l] = bv;
        }
    };

    auto compute = [&](int buf) {
        const uint32_t ab = a_frag + buf * TILE_B;
        const uint32_t bb = b_frag + buf * TILE_B;
#pragma unroll
        for (int ks = 0; ks < 4; ks++) {
            const uint32_t ko = ks * 32;    // 8 u32 = 32 bytes along k
            uint32_t bf[4][2];
            {
                uint32_t t0[4], t1[4];
                ldsm4(t0, bb + ko);                     // n-fragments 0,1
                ldsm4(t1, bb + 16 * TS * 4 + ko);      // n-fragments 2,3
                bf[0][0] = t0[0]; bf[0][1] = t0[1];
                bf[1][0] = t0[2]; bf[1][1] = t0[3];
                bf[2][0] = t1[0]; bf[2][1] = t1[1];
                bf[3][0] = t1[2]; bf[3][1] = t1[3];
            }
#pragma unroll
            for (int mi = 0; mi < 4; mi++) {
                uint32_t af[4];
                ldsm4(af, ab + mi * (16 * TS * 4) + ko);
#pragma unroll
                for (int ni = 0; ni < 4; ni++)
                    mma_tf32(acc[mi][ni], af, bf[ni]);
            }
        }
    };

    // Prologue: fill buffer 0
    load_regs(0);
    store_tiles(0);
    __syncthreads();

    int buf = 0;
    for (int kt = 0; kt < K; kt += 32) {
        const bool more = (kt + 32 < K);
        if (more) load_regs(kt + 32);
        compute(buf);
        if (more) {
            store_tiles(buf ^ 1);
            __syncthreads();
        }
        buf ^= 1;
    }

    // Epilogue
#pragma unroll
    for (int mi = 0; mi < 4; mi++) {
#pragma unroll
        for (int ni = 0; ni < 4; ni++) {
            const int row = row0 + wm + mi * 16;
            const int col = col0 + wn + ni * 8 + 2 * tg;
            float2 v01 = make_float2(acc[mi][ni][0], acc[mi][ni][1]);
            float2 v23 = make_float2(acc[mi][ni][2], acc[mi][ni][3]);
            *(float2*)&C[(size_t)(row + g    ) * Nc + col] = v01;
            *(float2*)&C[(size_t)(row + g + 8) * Nc + col] = v23;
        }
    }
}

// ---------------------------------------------------------------------------
// Flash attention (causal) with tf32 mma.sync. (unchanged — ~540 us)
// Grid (N/64, B*H), 128 threads = 4 warps.
// ---------------------------------------------------------------------------
#define ATT_SMEM_U32  (64 * 132 + 64 * 132 + 64 * 68)
#define ATT_SMEM_BYTES (ATT_SMEM_U32 * 4)

__global__ __launch_bounds__(128) void attn_mma()
{
    extern __shared__ uint32_t smu[];
    uint32_t* Qs  = smu;               // [64][132] tf32 bits
    uint32_t* KVs = Qs + 64 * 132;     // [64][132] tf32 bits (K, then V)
    uint32_t* Ss  = KVs + 64 * 132;    // [64][68]  tf32 bits (P)

    const int bh  = blockIdx.y;
    const int b   = bh >> 4;
    const int h   = bh & 15;
    const int m0  = blockIdx.x * 64;
    const int tid = threadIdx.x;
    const int wid = tid >> 5;
    const int lane = tid & 31;
    const int g   = lane >> 2;
    const int tg  = lane & 3;

    const int r0  = wid * 16 + g;
    const int r1  = r0 + 8;
    const int gr0 = m0 + r0;
    const int gr1 = m0 + r1;

    const float* Qg = g_qkv + ((size_t)(b * NN + m0)) * TDI + h * DD;
#pragma unroll
    for (int l = 0; l < 16; l++) {
        int fl = tid + l * 128;
        int r  = fl >> 5;
        int d4 = (fl & 31) * 4;
        float4 v = *(const float4*)(Qg + (size_t)r * TDI + d4);
        uint32_t* qp = &Qs[r * 132 + d4];
        qp[0] = tf32r(v.x * QK_SCALE);
        qp[1] = tf32r(v.y * QK_SCALE);
        qp[2] = tf32r(v.z * QK_SCALE);
        qp[3] = tf32r(v.w * QK_SCALE);
    }

    float m_r[2] = {-1e30f, -1e30f};
    float l_r[2] = {0.f, 0.f};
    float O[16][4];
#pragma unroll
    for (int ni = 0; ni < 16; ni++)
#pragma unroll
        for (int r = 0; r < 4; r++) O[ni][r] = 0.f;

    const int ntiles = blockIdx.x + 1;
    for (int t = 0; t < ntiles; t++) {
        const int k0 = t * 64;
        __syncthreads();

        const float* Kg = g_qkv + ((size_t)(b * NN + k0)) * TDI + DI + h * DD;
#pragma unroll
        for (int l = 0; l < 16; l++) {
            int fl = tid + l * 128;
            int r  = fl >> 5;
            int d4 = (fl & 31) * 4;
            float4 v = *(const float4*)(Kg + (size_t)r * TDI + d4);
            uint32_t* kd = &KVs[r * 132 + d4];
            kd[0] = tf32r(v.x); kd[1] = tf32r(v.y);
            kd[2] = tf32r(v.z); kd[3] = tf32r(v.w);
        }
        __syncthreads();

        float S[8][4];
#pragma unroll
        for (int ni = 0; ni < 8; ni++)
#pragma unroll
            for (int r = 0; r < 4; r++) S[ni][r] = 0.f;

#pragma unroll
        for (int ks = 0; ks < 16; ks++) {
            uint32_t a[4];
            const uint32_t* qb = &Qs[r0 * 132 + ks * 8 + tg];
            a[0] = qb[0];
            a[1] = qb[8 * 132];
            a[2] = qb[4];
            a[3] = qb[8 * 132 + 4];
#pragma unroll
            for (int ni = 0; ni < 8; ni++) {
                uint32_t bb[2];
                const uint32_t* kb = &KVs[(ni * 8 + g) * 132 + ks * 8 + tg];
                bb[0] = kb[0];
                bb[1] = kb[4];
                mma_tf32(S[ni], a, bb);
            }
        }

        if (t == ntiles - 1) {
#pragma unroll
            for (int ni = 0; ni < 8; ni++) {
                const int c = k0 + ni * 8 + 2 * tg;
                if (c     > gr0) S[ni][0] = -1e30f;
                if (c + 1 > gr0) S[ni][1] = -1e30f;
                if (c     > gr1) S[ni][2] = -1e30f;
                if (c + 1 > gr1) S[ni][3] = -1e30f;
            }
        }

        float mx0 = -1e30f, mx1 = -1e30f;
#pragma unroll
        for (int ni = 0; ni < 8; ni++) {
            mx0 = fmaxf(mx0, fmaxf(S[ni][0], S[ni][1]));
            mx1 = fmaxf(mx1, fmaxf(S[ni][2], S[ni][3]));
        }
        mx0 = fmaxf(mx0, __shfl_xor_sync(0xffffffffu, mx0, 1));
        mx0 = fmaxf(mx0, __shfl_xor_sync(0xffffffffu, mx0, 2));
        mx1 = fmaxf(mx1, __shfl_xor_sync(0xffffffffu, mx1, 1));
        mx1 = fmaxf(mx1, __shfl_xor_sync(0xffffffffu, mx1, 2));

        const float mn0 = fmaxf(m_r[0], mx0);
        const float mn1 = fmaxf(m_r[1], mx1);
        const float sc0 = __expf(m_r[0] - mn0);
        const float sc1 = __expf(m_r[1] - mn1);

        float sum0 = 0.f, sum1 = 0.f;
        uint32_t* s0 = &Ss[r0 * 68 + 2 * tg];
        uint32_t* s1 = &Ss[r1 * 68 + 2 * tg];
#pragma unroll
        for (int ni = 0; ni < 8; ni++) {
            float p00 = __expf(S[ni][0] - mn0);
            float p01 = __expf(S[ni][1] - mn0);
            float p10 = __expf(S[ni][2] - mn1);
            float p11 = __expf(S[ni][3] - mn1);
            sum0 += p00 + p01;
            sum1 += p10 + p11;
            s0[ni * 8 + 0] = tf32r(p00);
            s0[ni * 8 + 1] = tf32r(p01);
            s1[ni * 8 + 0] = tf32r(p10);
            s1[ni * 8 + 1] = tf32r(p11);
        }
        sum0 += __shfl_xor_sync(0xffffffffu, sum0, 1);
        sum0 += __shfl_xor_sync(0xffffffffu, sum0, 2);
        sum1 += __shfl_xor_sync(0xffffffffu, sum1, 1);
        sum1 += __shfl_xor_sync(0xffffffffu, sum1, 2);

        l_r[0] = l_r[0] * sc0 + sum0;  m_r[0] = mn0;
        l_r[1] = l_r[1] * sc1 + sum1;  m_r[1] = mn1;

#pragma unroll
        for (int ni = 0; ni < 16; ni++) {
            O[ni][0] *= sc0; O[ni][1] *= sc0;
            O[ni][2] *= sc1; O[ni][3] *= sc1;
        }

        __syncthreads();

        const float* Vg = g_qkv + ((size_t)(b * NN + k0)) * TDI + 2 * DI + h * DD;
#pragma unroll
        for (int l = 0; l < 16; l++) {
            int fl = tid + l * 128;
            int r  = fl >> 5;
            int d4 = (fl & 31) * 4;
            float4 v = *(const float4*)(Vg + (size_t)r * TDI + d4);
            uint32_t* vd = &KVs[r * 132 + d4];
            vd[0] = tf32r(v.x); vd[1] = tf32r(v.y);
            vd[2] = tf32r(v.z); vd[3] = tf32r(v.w);
        }
        __syncthreads();

#pragma unroll
        for (int ks = 0; ks < 8; ks++) {
            uint32_t a[4];
            const uint32_t* pb0 = &Ss[r0 * 68 + ks * 8 + tg];
            const uint32_t* pb1 = &Ss[r1 * 68 + ks * 8 + tg];
            a[0] = pb0[0];
            a[1] = pb1[0];
            a[2] = pb0[4];
            a[3] = pb1[4];
#pragma unroll
            for (int ni = 0; ni < 16; ni++) {
                uint32_t bb[2];
                const uint32_t* vb = &KVs[(ks * 8 + tg) * 132 + ni * 8 + g];
                bb[0] = vb[0];
                bb[1] = vb[4 * 132];
                mma_tf32(O[ni], a, bb);
            }
        }
    }

    const float inv0 = 1.0f / l_r[0];
    const float inv1 = 1.0f / l_r[1];
    float* O0 = g_att + ((size_t)(b * NN + gr0)) * DI + h * DD;
    float* O1 = g_att + ((size_t)(b * NN + gr1)) * DI + h * DD;
#pragma unroll
    for (int ni = 0; ni < 16; ni++) {
        const int c = ni * 8 + 2 * tg;
        *(float2*)&O0[c] = make_float2(O[ni][0] * inv0, O[ni][1] * inv0);
        *(float2*)&O1[c] = make_float2(O[ni][2] * inv1, O[ni][3] * inv1);
    }
}

// ---------------------------------------------------------------------------
// Launch
// ---------------------------------------------------------------------------
extern "C" void kernel_launch(void* const* d_in, const int* in_sizes, int n_in,
                              void* d_out, int out_size)
{
    const float* x     = (const float*)d_in[0];   // [2, 2048, 2048]
    const float* w_qkv = (const float*)d_in[1];   // [2048, 6144]
    const float* w_out = (const float*)d_in[2];   // [2048, 2048]
    float* out = (float*)d_out;                   // [2, 2048, 2048]

    cudaFuncSetAttribute(gemm_tf32,
                         cudaFuncAttributeMaxDynamicSharedMemorySize,
                         GEMM_SMEM_BYTES);
    cudaFuncSetAttribute(attn_mma,
                         cudaFuncAttributeMaxDynamicSharedMemorySize,
                         ATT_SMEM_BYTES);

    // 1) QKV projection: [4096, 2048] @ [2048, 6144]  -> g_qkv
    gemm_tf32<<<dim3(TDI / 128, (BB * NN) / 128), 256, GEMM_SMEM_BYTES>>>(
        x, w_qkv, nullptr, BB * NN, TDI, DIMM, 0);

    // 2) Causal flash attention (tf32 MMA): g_qkv -> g_att
    attn_mma<<<dim3(NN / 64, BB * HH), 128, ATT_SMEM_BYTES>>>();

    // 3) Output projection: [4096, 2048] @ [2048, 2048]  g_att -> out
    gemm_tf32<<<dim3(DIMM / 128, (BB * NN) / 128), 256, GEMM_SMEM_BYTES>>>(
        nullptr, w_out, out, BB * NN, DIMM, DIMM, 1);
}

// round 12
// speedup vs baseline: 4.8895x; 1.3995x over previous
#include <cuda_runtime.h>
#include <cuda_fp16.h>
#include <cstdint>
#include <cstddef>

// Problem constants
#define BB   2
#define NN   2048
#define DIMM 2048
#define HH   16
#define DD   128
#define DI   2048          // HEADS * DIM_HEAD
#define TDI  6144          // 3 * DI
#define QK_SCALE 0.08838834764831845f  // 128^-0.5

// Scratch
__device__ float g_qkv[(size_t)BB * NN * TDI];   // 96 MB
__device__ float g_att[(size_t)BB * NN * DI];    // 32 MB

// ---------------------------------------------------------------------------
// helpers
// ---------------------------------------------------------------------------
__device__ __forceinline__ uint32_t tf32r(float x) {
    uint32_t y;
    asm("cvt.rna.tf32.f32 %0, %1;" : "=r"(y) : "f"(x));
    return y;
}

__device__ __forceinline__ uint32_t pack_h2(float lo, float hi) {
    __half2 h = __floats2half2_rn(make_float2(lo, hi).x, make_float2(lo, hi).y);
    return *reinterpret_cast<uint32_t*>(&h);
}

__device__ __forceinline__ void mma_tf32(float c[4],
                                         const uint32_t a[4],
                                         const uint32_t b[2]) {
    asm volatile(
        "mma.sync.aligned.m16n8k8.row.col.f32.tf32.tf32.f32 "
        "{%0,%1,%2,%3}, {%4,%5,%6,%7}, {%8,%9}, {%0,%1,%2,%3};"
        : "+f"(c[0]), "+f"(c[1]), "+f"(c[2]), "+f"(c[3])
        : "r"(a[0]), "r"(a[1]), "r"(a[2]), "r"(a[3]),
          "r"(b[0]), "r"(b[1]));
}

__device__ __forceinline__ void mma_fp16(float c[4],
                                         const uint32_t a[4],
                                         const uint32_t b[2]) {
    asm volatile(
        "mma.sync.aligned.m16n8k16.row.col.f32.f16.f16.f32 "
        "{%0,%1,%2,%3}, {%4,%5,%6,%7}, {%8,%9}, {%0,%1,%2,%3};"
        : "+f"(c[0]), "+f"(c[1]), "+f"(c[2]), "+f"(c[3])
        : "r"(a[0]), "r"(a[1]), "r"(a[2]), "r"(a[3]),
          "r"(b[0]), "r"(b[1]));
}

__device__ __forceinline__ void ldsm4(uint32_t r[4], uint32_t saddr) {
    asm volatile("ldmatrix.sync.aligned.m8n8.x4.shared.b16 {%0,%1,%2,%3}, [%4];"
        : "=r"(r[0]), "=r"(r[1]), "=r"(r[2]), "=r"(r[3]) : "r"(saddr));
}

__device__ __forceinline__ void ldsm4t(uint32_t r[4], uint32_t saddr) {
    asm volatile("ldmatrix.sync.aligned.m8n8.x4.trans.shared.b16 {%0,%1,%2,%3}, [%4];"
        : "=r"(r[0]), "=r"(r[1]), "=r"(r[2]), "=r"(r[3]) : "r"(saddr));
}

// ---------------------------------------------------------------------------
// fp16 tensor-core GEMM (m16n8k16), double-buffered smem + ldmatrix.
// C[M,Nc] = A[M,K] @ B[K,Nc], row-major fp32 in/out; operands rounded to fp16.
// Block tile 128x128, BK=32, 256 threads = 8 warps (2m x 4n), warp 64x32.
// As: [m][k] halves, stride 40. Bs: [k][n] halves, stride 136 (natural layout;
// B fragments via ldmatrix.x4.trans). Per k16: 4 LDSM(A) + 2 LDSM.T(B) + 16 MMA.
// mode 0: A=param (x), C=g_qkv    mode 1: A=g_att, C=param (out)
// ---------------------------------------------------------------------------
#define SA 40                        // halves per A row
#define SB 136                       // halves per B row
#define ABUF_B (128 * SA * 2)        // 10240 bytes
#define BBUF_B (32 * SB * 2)         // 8704 bytes
#define GEMM_SMEM_BYTES (2 * ABUF_B + 2 * BBUF_B)   // 37888

__global__ __launch_bounds__(256, 2) void gemm_fp16(const float* __restrict__ Ap,
                                                    const float* __restrict__ B,
                                                    float* __restrict__ Cp,
                                                    int M, int Nc, int K, int mode)
{
    const float* A = (mode == 0) ? Ap : g_att;
    float*       C = (mode == 0) ? g_qkv : Cp;

    extern __shared__ char dsm[];
    const uint32_t sbase = (uint32_t)__cvta_generic_to_shared(dsm);

    const int tid  = threadIdx.x;
    const int row0 = blockIdx.y * 128;
    const int col0 = blockIdx.x * 128;
    const int wid  = tid >> 5;
    const int lane = tid & 31;
    const int g    = lane >> 2;
    const int tg   = lane & 3;
    const int wm   = (wid & 1) * 64;
    const int wn   = (wid >> 1) * 32;
    const int q    = lane >> 3;      // ldmatrix quad 0..3
    const int rr   = lane & 7;       // row within 8x8 matrix

    // Fragment base byte-offsets (within a buffer)
    const uint32_t a_off0 = (uint32_t)(((wm + (q & 1) * 8 + rr) * SA + (q >> 1) * 8) * 2);
    const uint32_t b_off0 = (uint32_t)((((q & 1) * 8 + rr) * SB + wn + (q >> 1) * 8) * 2);

    float acc[4][4][4];
#pragma unroll
    for (int mi = 0; mi < 4; mi++)
#pragma unroll
        for (int ni = 0; ni < 4; ni++)
#pragma unroll
            for (int r = 0; r < 4; r++) acc[mi][ni][r] = 0.f;

    // Global load mapping
    // A tile 128x32 f32: slot tid+256l -> row=(tid>>3)+32l, col=(tid&7)*4
    const int arow = tid >> 3, acol = (tid & 7) * 4;
    const float* Ag = A + (size_t)(row0 + arow) * K + acol;
    // B tile 32x128 f32: slot tid+256l -> krow=(tid>>5)+8l, col=(tid&31)*4
    const int brow = tid >> 5, bcol = (tid & 31) * 4;
    const float* Bg = B + (size_t)brow * Nc + col0 + bcol;

    float4 ra[4], rb[4];

    auto load_regs = [&](int kt) {
#pragma unroll
        for (int l = 0; l < 4; l++) {
            ra[l] = *(const float4*)(Ag + kt + (size_t)(32 * l) * K);
            rb[l] = *(const float4*)(Bg + (size_t)(kt + 8 * l) * Nc);
        }
    };

    auto store_tiles = [&](int buf) {
        char* As = dsm + buf * ABUF_B;
        char* Bs = dsm + 2 * ABUF_B + buf * BBUF_B;
#pragma unroll
        for (int l = 0; l < 4; l++) {
            uint2 av = make_uint2(pack_h2(ra[l].x, ra[l].y),
                                  pack_h2(ra[l].z, ra[l].w));
            *(uint2*)(As + ((arow + 32 * l) * SA + acol) * 2) = av;
            uint2 bv = make_uint2(pack_h2(rb[l].x, rb[l].y),
                                  pack_h2(rb[l].z, rb[l].w));
            *(uint2*)(Bs + ((brow + 8 * l) * SB + bcol) * 2) = bv;
        }
    };

    auto compute = [&](int buf) {
        const uint32_t ab = sbase + buf * ABUF_B + a_off0;
        const uint32_t bb = sbase + 2 * ABUF_B + buf * BBUF_B + b_off0;
#pragma unroll
        for (int ks = 0; ks < 2; ks++) {           // two k16 steps per chunk
            uint32_t bf[4][2];
            {
                uint32_t t0[4], t1[4];
                ldsm4t(t0, bb + ks * (16 * SB * 2));        // n 0..15
                ldsm4t(t1, bb + ks * (16 * SB * 2) + 32);   // n 16..31
                bf[0][0] = t0[0]; bf[0][1] = t0[1];
                bf[1][0] = t0[2]; bf[1][1] = t0[3];
                bf[2][0] = t1[0]; bf[2][1] = t1[1];
                bf[3][0] = t1[2]; bf[3][1] = t1[3];
            }
#pragma unroll
            for (int mi = 0; mi < 4; mi++) {
                uint32_t af[4];
                ldsm4(af, ab + mi * (16 * SA * 2) + ks * 32);
#pragma unroll
                for (int ni = 0; ni < 4; ni++)
                    mma_fp16(acc[mi][ni], af, bf[ni]);
            }
        }
    };

    // Prologue: fill buffer 0
    load_regs(0);
    store_tiles(0);
    __syncthreads();

    int buf = 0;
    for (int kt = 0; kt < K; kt += 32) {
        const bool more = (kt + 32 < K);
        if (more) load_regs(kt + 32);
        compute(buf);
        if (more) {
            store_tiles(buf ^ 1);
            __syncthreads();
        }
        buf ^= 1;
    }

    // Epilogue
#pragma unroll
    for (int mi = 0; mi < 4; mi++) {
#pragma unroll
        for (int ni = 0; ni < 4; ni++) {
            const int row = row0 + wm + mi * 16;
            const int col = col0 + wn + ni * 8 + 2 * tg;
            float2 v01 = make_float2(acc[mi][ni][0], acc[mi][ni][1]);
            float2 v23 = make_float2(acc[mi][ni][2], acc[mi][ni][3]);
            *(float2*)&C[(size_t)(row + g    ) * Nc + col] = v01;
            *(float2*)&C[(size_t)(row + g + 8) * Nc + col] = v23;
        }
    }
}

// ---------------------------------------------------------------------------
// Flash attention (causal) with tf32 mma.sync. (unchanged — ~530 us)
// Grid (N/64, B*H), 128 threads = 4 warps.
// ---------------------------------------------------------------------------
#define ATT_SMEM_U32  (64 * 132 + 64 * 132 + 64 * 68)
#define ATT_SMEM_BYTES (ATT_SMEM_U32 * 4)

__global__ __launch_bounds__(128) void attn_mma()
{
    extern __shared__ uint32_t smu[];
    uint32_t* Qs  = smu;
    uint32_t* KVs = Qs + 64 * 132;
    uint32_t* Ss  = KVs + 64 * 132;

    const int bh  = blockIdx.y;
    const int b   = bh >> 4;
    const int h   = bh & 15;
    const int m0  = blockIdx.x * 64;
    const int tid = threadIdx.x;
    const int wid = tid >> 5;
    const int lane = tid & 31;
    const int g   = lane >> 2;
    const int tg  = lane & 3;

    const int r0  = wid * 16 + g;
    const int r1  = r0 + 8;
    const int gr0 = m0 + r0;
    const int gr1 = m0 + r1;

    const float* Qg = g_qkv + ((size_t)(b * NN + m0)) * TDI + h * DD;
#pragma unroll
    for (int l = 0; l < 16; l++) {
        int fl = tid + l * 128;
        int r  = fl >> 5;
        int d4 = (fl & 31) * 4;
        float4 v = *(const float4*)(Qg + (size_t)r * TDI + d4);
        uint32_t* qp = &Qs[r * 132 + d4];
        qp[0] = tf32r(v.x * QK_SCALE);
        qp[1] = tf32r(v.y * QK_SCALE);
        qp[2] = tf32r(v.z * QK_SCALE);
        qp[3] = tf32r(v.w * QK_SCALE);
    }

    float m_r[2] = {-1e30f, -1e30f};
    float l_r[2] = {0.f, 0.f};
    float O[16][4];
#pragma unroll
    for (int ni = 0; ni < 16; ni++)
#pragma unroll
        for (int r = 0; r < 4; r++) O[ni][r] = 0.f;

    const int ntiles = blockIdx.x + 1;
    for (int t = 0; t < ntiles; t++) {
        const int k0 = t * 64;
        __syncthreads();

        const float* Kg = g_qkv + ((size_t)(b * NN + k0)) * TDI + DI + h * DD;
#pragma unroll
        for (int l = 0; l < 16; l++) {
            int fl = tid + l * 128;
            int r  = fl >> 5;
            int d4 = (fl & 31) * 4;
            float4 v = *(const float4*)(Kg + (size_t)r * TDI + d4);
            uint32_t* kd = &KVs[r * 132 + d4];
            kd[0] = tf32r(v.x); kd[1] = tf32r(v.y);
            kd[2] = tf32r(v.z); kd[3] = tf32r(v.w);
        }
        __syncthreads();

        float S[8][4];
#pragma unroll
        for (int ni = 0; ni < 8; ni++)
#pragma unroll
            for (int r = 0; r < 4; r++) S[ni][r] = 0.f;

#pragma unroll
        for (int ks = 0; ks < 16; ks++) {
            uint32_t a[4];
            const uint32_t* qb = &Qs[r0 * 132 + ks * 8 + tg];
            a[0] = qb[0];
            a[1] = qb[8 * 132];
            a[2] = qb[4];
            a[3] = qb[8 * 132 + 4];
#pragma unroll
            for (int ni = 0; ni < 8; ni++) {
                uint32_t bb[2];
                const uint32_t* kb = &KVs[(ni * 8 + g) * 132 + ks * 8 + tg];
                bb[0] = kb[0];
                bb[1] = kb[4];
                mma_tf32(S[ni], a, bb);
            }
        }

        if (t == ntiles - 1) {
#pragma unroll
            for (int ni = 0; ni < 8; ni++) {
                const int c = k0 + ni * 8 + 2 * tg;
                if (c     > gr0) S[ni][0] = -1e30f;
                if (c + 1 > gr0) S[ni][1] = -1e30f;
                if (c     > gr1) S[ni][2] = -1e30f;
                if (c + 1 > gr1) S[ni][3] = -1e30f;
            }
        }

        float mx0 = -1e30f, mx1 = -1e30f;
#pragma unroll
        for (int ni = 0; ni < 8; ni++) {
            mx0 = fmaxf(mx0, fmaxf(S[ni][0], S[ni][1]));
            mx1 = fmaxf(mx1, fmaxf(S[ni][2], S[ni][3]));
        }
        mx0 = fmaxf(mx0, __shfl_xor_sync(0xffffffffu, mx0, 1));
        mx0 = fmaxf(mx0, __shfl_xor_sync(0xffffffffu, mx0, 2));
        mx1 = fmaxf(mx1, __shfl_xor_sync(0xffffffffu, mx1, 1));
        mx1 = fmaxf(mx1, __shfl_xor_sync(0xffffffffu, mx1, 2));

        const float mn0 = fmaxf(m_r[0], mx0);
        const float mn1 = fmaxf(m_r[1], mx1);
        const float sc0 = __expf(m_r[0] - mn0);
        const float sc1 = __expf(m_r[1] - mn1);

        float sum0 = 0.f, sum1 = 0.f;
        uint32_t* s0 = &Ss[r0 * 68 + 2 * tg];
        uint32_t* s1 = &Ss[r1 * 68 + 2 * tg];
#pragma unroll
        for (int ni = 0; ni < 8; ni++) {
            float p00 = __expf(S[ni][0] - mn0);
            float p01 = __expf(S[ni][1] - mn0);
            float p10 = __expf(S[ni][2] - mn1);
            float p11 = __expf(S[ni][3] - mn1);
            sum0 += p00 + p01;
            sum1 += p10 + p11;
            s0[ni * 8 + 0] = tf32r(p00);
            s0[ni * 8 + 1] = tf32r(p01);
            s1[ni * 8 + 0] = tf32r(p10);
            s1[ni * 8 + 1] = tf32r(p11);
        }
        sum0 += __shfl_xor_sync(0xffffffffu, sum0, 1);
        sum0 += __shfl_xor_sync(0xffffffffu, sum0, 2);
        sum1 += __shfl_xor_sync(0xffffffffu, sum1, 1);
        sum1 += __shfl_xor_sync(0xffffffffu, sum1, 2);

        l_r[0] = l_r[0] * sc0 + sum0;  m_r[0] = mn0;
        l_r[1] = l_r[1] * sc1 + sum1;  m_r[1] = mn1;

#pragma unroll
        for (int ni = 0; ni < 16; ni++) {
            O[ni][0] *= sc0; O[ni][1] *= sc0;
            O[ni][2] *= sc1; O[ni][3] *= sc1;
        }

        __syncthreads();

        const float* Vg = g_qkv + ((size_t)(b * NN + k0)) * TDI + 2 * DI + h * DD;
#pragma unroll
        for (int l = 0; l < 16; l++) {
            int fl = tid + l * 128;
            int r  = fl >> 5;
            int d4 = (fl & 31) * 4;
            float4 v = *(const float4*)(Vg + (size_t)r * TDI + d4);
            uint32_t* vd = &KVs[r * 132 + d4];
            vd[0] = tf32r(v.x); vd[1] = tf32r(v.y);
            vd[2] = tf32r(v.z); vd[3] = tf32r(v.w);
        }
        __syncthreads();

#pragma unroll
        for (int ks = 0; ks < 8; ks++) {
            uint32_t a[4];
            const uint32_t* pb0 = &Ss[r0 * 68 + ks * 8 + tg];
            const uint32_t* pb1 = &Ss[r1 * 68 + ks * 8 + tg];
            a[0] = pb0[0];
            a[1] = pb1[0];
            a[2] = pb0[4];
            a[3] = pb1[4];
#pragma unroll
            for (int ni = 0; ni < 16; ni++) {
                uint32_t bb[2];
                const uint32_t* vb = &KVs[(ks * 8 + tg) * 132 + ni * 8 + g];
                bb[0] = vb[0];
                bb[1] = vb[4 * 132];
                mma_tf32(O[ni], a, bb);
            }
        }
    }

    const float inv0 = 1.0f / l_r[0];
    const float inv1 = 1.0f / l_r[1];
    float* O0 = g_att + ((size_t)(b * NN + gr0)) * DI + h * DD;
    float* O1 = g_att + ((size_t)(b * NN + gr1)) * DI + h * DD;
#pragma unroll
    for (int ni = 0; ni < 16; ni++) {
        const int c = ni * 8 + 2 * tg;
        *(float2*)&O0[c] = make_float2(O[ni][0] * inv0, O[ni][1] * inv0);
        *(float2*)&O1[c] = make_float2(O[ni][2] * inv1, O[ni][3] * inv1);
    }
}

// ---------------------------------------------------------------------------
// Launch
// ---------------------------------------------------------------------------
extern "C" void kernel_launch(void* const* d_in, const int* in_sizes, int n_in,
                              void* d_out, int out_size)
{
    const float* x     = (const float*)d_in[0];   // [2, 2048, 2048]
    const float* w_qkv = (const float*)d_in[1];   // [2048, 6144]
    const float* w_out = (const float*)d_in[2];   // [2048, 2048]
    float* out = (float*)d_out;                   // [2, 2048, 2048]

    cudaFuncSetAttribute(gemm_fp16,
                         cudaFuncAttributeMaxDynamicSharedMemorySize,
                         GEMM_SMEM_BYTES);
    cudaFuncSetAttribute(attn_mma,
                         cudaFuncAttributeMaxDynamicSharedMemorySize,
                         ATT_SMEM_BYTES);

    // 1) QKV projection: [4096, 2048] @ [2048, 6144]  -> g_qkv
    gemm_fp16<<<dim3(TDI / 128, (BB * NN) / 128), 256, GEMM_SMEM_BYTES>>>(
        x, w_qkv, nullptr, BB * NN, TDI, DIMM, 0);

    // 2) Causal flash attention (tf32 MMA): g_qkv -> g_att
    attn_mma<<<dim3(NN / 64, BB * HH), 128, ATT_SMEM_BYTES>>>();

    // 3) Output projection: [4096, 2048] @ [2048, 2048]  g_att -> out
    gemm_fp16<<<dim3(DIMM / 128, (BB * NN) / 128), 256, GEMM_SMEM_BYTES>>>(
        nullptr, w_out, out, BB * NN, DIMM, DIMM, 1);
}

// round 13
// speedup vs baseline: 4.8982x; 1.0018x over previous
#include <cuda_runtime.h>
#include <cuda_fp16.h>
#include <cstdint>
#include <cstddef>

// Problem constants
#define BB   2
#define NN   2048
#define DIMM 2048
#define HH   16
#define DD   128
#define DI   2048          // HEADS * DIM_HEAD
#define TDI  6144          // 3 * DI
#define QK_SCALE 0.08838834764831845f  // 128^-0.5

// Scratch
__device__ float g_qkv[(size_t)BB * NN * TDI];   // 96 MB
__device__ float g_att[(size_t)BB * NN * DI];    // 32 MB

// ---------------------------------------------------------------------------
// helpers
// ---------------------------------------------------------------------------
__device__ __forceinline__ uint32_t tf32r(float x) {
    uint32_t y;
    asm("cvt.rna.tf32.f32 %0, %1;" : "=r"(y) : "f"(x));
    return y;
}

__device__ __forceinline__ uint32_t pack_h2(float lo, float hi) {
    __half2 h = __floats2half2_rn(make_float2(lo, hi).x, make_float2(lo, hi).y);
    return *reinterpret_cast<uint32_t*>(&h);
}

__device__ __forceinline__ void mma_tf32(float c[4],
                                         const uint32_t a[4],
                                         const uint32_t b[2]) {
    asm volatile(
        "mma.sync.aligned.m16n8k8.row.col.f32.tf32.tf32.f32 "
        "{%0,%1,%2,%3}, {%4,%5,%6,%7}, {%8,%9}, {%0,%1,%2,%3};"
        : "+f"(c[0]), "+f"(c[1]), "+f"(c[2]), "+f"(c[3])
        : "r"(a[0]), "r"(a[1]), "r"(a[2]), "r"(a[3]),
          "r"(b[0]), "r"(b[1]));
}

__device__ __forceinline__ void mma_fp16(float c[4],
                                         const uint32_t a[4],
                                         const uint32_t b[2]) {
    asm volatile(
        "mma.sync.aligned.m16n8k16.row.col.f32.f16.f16.f32 "
        "{%0,%1,%2,%3}, {%4,%5,%6,%7}, {%8,%9}, {%0,%1,%2,%3};"
        : "+f"(c[0]), "+f"(c[1]), "+f"(c[2]), "+f"(c[3])
        : "r"(a[0]), "r"(a[1]), "r"(a[2]), "r"(a[3]),
          "r"(b[0]), "r"(b[1]));
}

__device__ __forceinline__ void ldsm4(uint32_t r[4], uint32_t saddr) {
    asm volatile("ldmatrix.sync.aligned.m8n8.x4.shared.b16 {%0,%1,%2,%3}, [%4];"
        : "=r"(r[0]), "=r"(r[1]), "=r"(r[2]), "=r"(r[3]) : "r"(saddr));
}

__device__ __forceinline__ void ldsm4t(uint32_t r[4], uint32_t saddr) {
    asm volatile("ldmatrix.sync.aligned.m8n8.x4.trans.shared.b16 {%0,%1,%2,%3}, [%4];"
        : "=r"(r[0]), "=r"(r[1]), "=r"(r[2]), "=r"(r[3]) : "r"(saddr));
}

// ---------------------------------------------------------------------------
// fp16 tensor-core GEMM (m16n8k16), double-buffered smem + ldmatrix.
// C[M,Nc] = A[M,K] @ B[K,Nc], row-major fp32 in/out; operands rounded to fp16.
// Block tile 128x128, BK=32, 256 threads = 8 warps (2m x 4n), warp 64x32.
// As: [m][k] halves, stride 40. Bs: [k][n] halves, stride 136 (natural layout;
// B fragments via ldmatrix.x4.trans). Per k16: 4 LDSM(A) + 2 LDSM.T(B) + 16 MMA.
// mode 0: A=param (x), C=g_qkv    mode 1: A=g_att, C=param (out)
// ---------------------------------------------------------------------------
#define SA 40                        // halves per A row
#define SB 136                       // halves per B row
#define ABUF_B (128 * SA * 2)        // 10240 bytes
#define BBUF_B (32 * SB * 2)         // 8704 bytes
#define GEMM_SMEM_BYTES (2 * ABUF_B + 2 * BBUF_B)   // 37888

__global__ __launch_bounds__(256, 2) void gemm_fp16(const float* __restrict__ Ap,
                                                    const float* __restrict__ B,
                                                    float* __restrict__ Cp,
                                                    int M, int Nc, int K, int mode)
{
    const float* A = (mode == 0) ? Ap : g_att;
    float*       C = (mode == 0) ? g_qkv : Cp;

    extern __shared__ char dsm[];
    const uint32_t sbase = (uint32_t)__cvta_generic_to_shared(dsm);

    const int tid  = threadIdx.x;
    const int row0 = blockIdx.y * 128;
    const int col0 = blockIdx.x * 128;
    const int wid  = tid >> 5;
    const int lane = tid & 31;
    const int g    = lane >> 2;
    const int tg   = lane & 3;
    const int wm   = (wid & 1) * 64;
    const int wn   = (wid >> 1) * 32;
    const int q    = lane >> 3;      // ldmatrix quad 0..3
    const int rr   = lane & 7;       // row within 8x8 matrix

    // Fragment base byte-offsets (within a buffer)
    const uint32_t a_off0 = (uint32_t)(((wm + (q & 1) * 8 + rr) * SA + (q >> 1) * 8) * 2);
    const uint32_t b_off0 = (uint32_t)((((q & 1) * 8 + rr) * SB + wn + (q >> 1) * 8) * 2);

    float acc[4][4][4];
#pragma unroll
    for (int mi = 0; mi < 4; mi++)
#pragma unroll
        for (int ni = 0; ni < 4; ni++)
#pragma unroll
            for (int r = 0; r < 4; r++) acc[mi][ni][r] = 0.f;

    // Global load mapping
    // A tile 128x32 f32: slot tid+256l -> row=(tid>>3)+32l, col=(tid&7)*4
    const int arow = tid >> 3, acol = (tid & 7) * 4;
    const float* Ag = A + (size_t)(row0 + arow) * K + acol;
    // B tile 32x128 f32: slot tid+256l -> krow=(tid>>5)+8l, col=(tid&31)*4
    const int brow = tid >> 5, bcol = (tid & 31) * 4;
    const float* Bg = B + (size_t)brow * Nc + col0 + bcol;

    float4 ra[4], rb[4];

    auto load_regs = [&](int kt) {
#pragma unroll
        for (int l = 0; l < 4; l++) {
            ra[l] = *(const float4*)(Ag + kt + (size_t)(32 * l) * K);
            rb[l] = *(const float4*)(Bg + (size_t)(kt + 8 * l) * Nc);
        }
    };

    auto store_tiles = [&](int buf) {
        char* As = dsm + buf * ABUF_B;
        char* Bs = dsm + 2 * ABUF_B + buf * BBUF_B;
#pragma unroll
        for (int l = 0; l < 4; l++) {
            uint2 av = make_uint2(pack_h2(ra[l].x, ra[l].y),
                                  pack_h2(ra[l].z, ra[l].w));
            *(uint2*)(As + ((arow + 32 * l) * SA + acol) * 2) = av;
            uint2 bv = make_uint2(pack_h2(rb[l].x, rb[l].y),
                                  pack_h2(rb[l].z, rb[l].w));
            *(uint2*)(Bs + ((brow + 8 * l) * SB + bcol) * 2) = bv;
        }
    };

    auto compute = [&](int buf) {
        const uint32_t ab = sbase + buf * ABUF_B + a_off0;
        const uint32_t bb = sbase + 2 * ABUF_B + buf * BBUF_B + b_off0;
#pragma unroll
        for (int ks = 0; ks < 2; ks++) {           // two k16 steps per chunk
            uint32_t bf[4][2];
            {
                uint32_t t0[4], t1[4];
                ldsm4t(t0, bb + ks * (16 * SB * 2));        // n 0..15
                ldsm4t(t1, bb + ks * (16 * SB * 2) + 32);   // n 16..31
                bf[0][0] = t0[0]; bf[0][1] = t0[1];
                bf[1][0] = t0[2]; bf[1][1] = t0[3];
                bf[2][0] = t1[0]; bf[2][1] = t1[1];
                bf[3][0] = t1[2]; bf[3][1] = t1[3];
            }
#pragma unroll
            for (int mi = 0; mi < 4; mi++) {
                uint32_t af[4];
                ldsm4(af, ab + mi * (16 * SA * 2) + ks * 32);
#pragma unroll
                for (int ni = 0; ni < 4; ni++)
                    mma_fp16(acc[mi][ni], af, bf[ni]);
            }
        }
    };

    // Prologue: fill buffer 0
    load_regs(0);
    store_tiles(0);
    __syncthreads();

    int buf = 0;
    for (int kt = 0; kt < K; kt += 32) {
        const bool more = (kt + 32 < K);
        if (more) load_regs(kt + 32);
        compute(buf);
        if (more) {
            store_tiles(buf ^ 1);
            __syncthreads();
        }
        buf ^= 1;
    }

    // Epilogue
#pragma unroll
    for (int mi = 0; mi < 4; mi++) {
#pragma unroll
        for (int ni = 0; ni < 4; ni++) {
            const int row = row0 + wm + mi * 16;
            const int col = col0 + wn + ni * 8 + 2 * tg;
            float2 v01 = make_float2(acc[mi][ni][0], acc[mi][ni][1]);
            float2 v23 = make_float2(acc[mi][ni][2], acc[mi][ni][3]);
            *(float2*)&C[(size_t)(row + g    ) * Nc + col] = v01;
            *(float2*)&C[(size_t)(row + g + 8) * Nc + col] = v23;
        }
    }
}

// ---------------------------------------------------------------------------
// Flash attention (causal) with tf32 mma.sync. (unchanged — ~530 us)
// Grid (N/64, B*H), 128 threads = 4 warps.
// ---------------------------------------------------------------------------
#define ATT_SMEM_U32  (64 * 132 + 64 * 132 + 64 * 68)
#define ATT_SMEM_BYTES (ATT_SMEM_U32 * 4)

__global__ __launch_bounds__(128) void attn_mma()
{
    extern __shared__ uint32_t smu[];
    uint32_t* Qs  = smu;
    uint32_t* KVs = Qs + 64 * 132;
    uint32_t* Ss  = KVs + 64 * 132;

    const int bh  = blockIdx.y;
    const int b   = bh >> 4;
    const int h   = bh & 15;
    const int m0  = blockIdx.x * 64;
    const int tid = threadIdx.x;
    const int wid = tid >> 5;
    const int lane = tid & 31;
    const int g   = lane >> 2;
    const int tg  = lane & 3;

    const int r0  = wid * 16 + g;
    const int r1  = r0 + 8;
    const int gr0 = m0 + r0;
    const int gr1 = m0 + r1;

    const float* Qg = g_qkv + ((size_t)(b * NN + m0)) * TDI + h * DD;
#pragma unroll
    for (int l = 0; l < 16; l++) {
        int fl = tid + l * 128;
        int r  = fl >> 5;
        int d4 = (fl & 31) * 4;
        float4 v = *(const float4*)(Qg + (size_t)r * TDI + d4);
        uint32_t* qp = &Qs[r * 132 + d4];
        qp[0] = tf32r(v.x * QK_SCALE);
        qp[1] = tf32r(v.y * QK_SCALE);
        qp[2] = tf32r(v.z * QK_SCALE);
        qp[3] = tf32r(v.w * QK_SCALE);
    }

    float m_r[2] = {-1e30f, -1e30f};
    float l_r[2] = {0.f, 0.f};
    float O[16][4];
#pragma unroll
    for (int ni = 0; ni < 16; ni++)
#pragma unroll
        for (int r = 0; r < 4; r++) O[ni][r] = 0.f;

    const int ntiles = blockIdx.x + 1;
    for (int t = 0; t < ntiles; t++) {
        const int k0 = t * 64;
        __syncthreads();

        const float* Kg = g_qkv + ((size_t)(b * NN + k0)) * TDI + DI + h * DD;
#pragma unroll
        for (int l = 0; l < 16; l++) {
            int fl = tid + l * 128;
            int r  = fl >> 5;
            int d4 = (fl & 31) * 4;
            float4 v = *(const float4*)(Kg + (size_t)r * TDI + d4);
            uint32_t* kd = &KVs[r * 132 + d4];
            kd[0] = tf32r(v.x); kd[1] = tf32r(v.y);
            kd[2] = tf32r(v.z); kd[3] = tf32r(v.w);
        }
        __syncthreads();

        float S[8][4];
#pragma unroll
        for (int ni = 0; ni < 8; ni++)
#pragma unroll
            for (int r = 0; r < 4; r++) S[ni][r] = 0.f;

#pragma unroll
        for (int ks = 0; ks < 16; ks++) {
            uint32_t a[4];
            const uint32_t* qb = &Qs[r0 * 132 + ks * 8 + tg];
            a[0] = qb[0];
            a[1] = qb[8 * 132];
            a[2] = qb[4];
            a[3] = qb[8 * 132 + 4];
#pragma unroll
            for (int ni = 0; ni < 8; ni++) {
                uint32_t bb[2];
                const uint32_t* kb = &KVs[(ni * 8 + g) * 132 + ks * 8 + tg];
                bb[0] = kb[0];
                bb[1] = kb[4];
                mma_tf32(S[ni], a, bb);
            }
        }

        if (t == ntiles - 1) {
#pragma unroll
            for (int ni = 0; ni < 8; ni++) {
                const int c = k0 + ni * 8 + 2 * tg;
                if (c     > gr0) S[ni][0] = -1e30f;
                if (c + 1 > gr0) S[ni][1] = -1e30f;
                if (c     > gr1) S[ni][2] = -1e30f;
                if (c + 1 > gr1) S[ni][3] = -1e30f;
            }
        }

        float mx0 = -1e30f, mx1 = -1e30f;
#pragma unroll
        for (int ni = 0; ni < 8; ni++) {
            mx0 = fmaxf(mx0, fmaxf(S[ni][0], S[ni][1]));
            mx1 = fmaxf(mx1, fmaxf(S[ni][2], S[ni][3]));
        }
        mx0 = fmaxf(mx0, __shfl_xor_sync(0xffffffffu, mx0, 1));
        mx0 = fmaxf(mx0, __shfl_xor_sync(0xffffffffu, mx0, 2));
        mx1 = fmaxf(mx1, __shfl_xor_sync(0xffffffffu, mx1, 1));
        mx1 = fmaxf(mx1, __shfl_xor_sync(0xffffffffu, mx1, 2));

        const float mn0 = fmaxf(m_r[0], mx0);
        const float mn1 = fmaxf(m_r[1], mx1);
        const float sc0 = __expf(m_r[0] - mn0);
        const float sc1 = __expf(m_r[1] - mn1);

        float sum0 = 0.f, sum1 = 0.f;
        uint32_t* s0 = &Ss[r0 * 68 + 2 * tg];
        uint32_t* s1 = &Ss[r1 * 68 + 2 * tg];
#pragma unroll
        for (int ni = 0; ni < 8; ni++) {
            float p00 = __expf(S[ni][0] - mn0);
            float p01 = __expf(S[ni][1] - mn0);
            float p10 = __expf(S[ni][2] - mn1);
            float p11 = __expf(S[ni][3] - mn1);
            sum0 += p00 + p01;
            sum1 += p10 + p11;
            s0[ni * 8 + 0] = tf32r(p00);
            s0[ni * 8 + 1] = tf32r(p01);
            s1[ni * 8 + 0] = tf32r(p10);
            s1[ni * 8 + 1] = tf32r(p11);
        }
        sum0 += __shfl_xor_sync(0xffffffffu, sum0, 1);
        sum0 += __shfl_xor_sync(0xffffffffu, sum0, 2);
        sum1 += __shfl_xor_sync(0xffffffffu, sum1, 1);
        sum1 += __shfl_xor_sync(0xffffffffu, sum1, 2);

        l_r[0] = l_r[0] * sc0 + sum0;  m_r[0] = mn0;
        l_r[1] = l_r[1] * sc1 + sum1;  m_r[1] = mn1;

#pragma unroll
        for (int ni = 0; ni < 16; ni++) {
            O[ni][0] *= sc0; O[ni][1] *= sc0;
            O[ni][2] *= sc1; O[ni][3] *= sc1;
        }

        __syncthreads();

        const float* Vg = g_qkv + ((size_t)(b * NN + k0)) * TDI + 2 * DI + h * DD;
#pragma unroll
        for (int l = 0; l < 16; l++) {
            int fl = tid + l * 128;
            int r  = fl >> 5;
            int d4 = (fl & 31) * 4;
            float4 v = *(const float4*)(Vg + (size_t)r * TDI + d4);
            uint32_t* vd = &KVs[r * 132 + d4];
            vd[0] = tf32r(v.x); vd[1] = tf32r(v.y);
            vd[2] = tf32r(v.z); vd[3] = tf32r(v.w);
        }
        __syncthreads();

#pragma unroll
        for (int ks = 0; ks < 8; ks++) {
            uint32_t a[4];
            const uint32_t* pb0 = &Ss[r0 * 68 + ks * 8 + tg];
            const uint32_t* pb1 = &Ss[r1 * 68 + ks * 8 + tg];
            a[0] = pb0[0];
            a[1] = pb1[0];
            a[2] = pb0[4];
            a[3] = pb1[4];
#pragma unroll
            for (int ni = 0; ni < 16; ni++) {
                uint32_t bb[2];
                const uint32_t* vb = &KVs[(ks * 8 + tg) * 132 + ni * 8 + g];
                bb[0] = vb[0];
                bb[1] = vb[4 * 132];
                mma_tf32(O[ni], a, bb);
            }
        }
    }

    const float inv0 = 1.0f / l_r[0];
    const float inv1 = 1.0f / l_r[1];
    float* O0 = g_att + ((size_t)(b * NN + gr0)) * DI + h * DD;
    float* O1 = g_att + ((size_t)(b * NN + gr1)) * DI + h * DD;
#pragma unroll
    for (int ni = 0; ni < 16; ni++) {
        const int c = ni * 8 + 2 * tg;
        *(float2*)&O0[c] = make_float2(O[ni][0] * inv0, O[ni][1] * inv0);
        *(float2*)&O1[c] = make_float2(O[ni][2] * inv1, O[ni][3] * inv1);
    }
}

// ---------------------------------------------------------------------------
// Launch
// ---------------------------------------------------------------------------
extern "C" void kernel_launch(void* const* d_in, const int* in_sizes, int n_in,
                              void* d_out, int out_size)
{
    const float* x     = (const float*)d_in[0];   // [2, 2048, 2048]
    const float* w_qkv = (const float*)d_in[1];   // [2048, 6144]
    const float* w_out = (const float*)d_in[2];   // [2048, 2048]
    float* out = (float*)d_out;                   // [2, 2048, 2048]

    cudaFuncSetAttribute(gemm_fp16,
                         cudaFuncAttributeMaxDynamicSharedMemorySize,
                         GEMM_SMEM_BYTES);
    cudaFuncSetAttribute(attn_mma,
                         cudaFuncAttributeMaxDynamicSharedMemorySize,
                         ATT_SMEM_BYTES);

    // 1) QKV projection: [4096, 2048] @ [2048, 6144]  -> g_qkv
    gemm_fp16<<<dim3(TDI / 128, (BB * NN) / 128), 256, GEMM_SMEM_BYTES>>>(
        x, w_qkv, nullptr, BB * NN, TDI, DIMM, 0);

    // 2) Causal flash attention (tf32 MMA): g_qkv -> g_att
    attn_mma<<<dim3(NN / 64, BB * HH), 128, ATT_SMEM_BYTES>>>();

    // 3) Output projection: [4096, 2048] @ [2048, 2048]  g_att -> out
    gemm_fp16<<<dim3(DIMM / 128, (BB * NN) / 128), 256, GEMM_SMEM_BYTES>>>(
        nullptr, w_out, out, BB * NN, DIMM, DIMM, 1);
}

// round 14
// speedup vs baseline: 6.4232x; 1.3114x over previous
#include <cuda_runtime.h>
#include <cuda_fp16.h>
#include <cstdint>
#include <cstddef>

// Problem constants
#define BB   2
#define NN   2048
#define DIMM 2048
#define HH   16
#define DD   128
#define DI   2048          // HEADS * DIM_HEAD
#define TDI  6144          // 3 * DI
#define QK_SCALE 0.08838834764831845f  // 128^-0.5

// Scratch
__device__ float g_qkv[(size_t)BB * NN * TDI];   // 96 MB
__device__ float g_att[(size_t)BB * NN * DI];    // 32 MB

// ---------------------------------------------------------------------------
// helpers
// ---------------------------------------------------------------------------
__device__ __forceinline__ uint32_t pack_h2(float lo, float hi) {
    __half2 h = __floats2half2_rn(lo, hi);
    return *reinterpret_cast<uint32_t*>(&h);
}

__device__ __forceinline__ void mma_fp16(float c[4],
                                         const uint32_t a[4],
                                         const uint32_t b0, const uint32_t b1) {
    asm volatile(
        "mma.sync.aligned.m16n8k16.row.col.f32.f16.f16.f32 "
        "{%0,%1,%2,%3}, {%4,%5,%6,%7}, {%8,%9}, {%0,%1,%2,%3};"
        : "+f"(c[0]), "+f"(c[1]), "+f"(c[2]), "+f"(c[3])
        : "r"(a[0]), "r"(a[1]), "r"(a[2]), "r"(a[3]),
          "r"(b0), "r"(b1));
}

__device__ __forceinline__ void ldsm4(uint32_t r[4], uint32_t saddr) {
    asm volatile("ldmatrix.sync.aligned.m8n8.x4.shared.b16 {%0,%1,%2,%3}, [%4];"
        : "=r"(r[0]), "=r"(r[1]), "=r"(r[2]), "=r"(r[3]) : "r"(saddr));
}

__device__ __forceinline__ void ldsm4t(uint32_t r[4], uint32_t saddr) {
    asm volatile("ldmatrix.sync.aligned.m8n8.x4.trans.shared.b16 {%0,%1,%2,%3}, [%4];"
        : "=r"(r[0]), "=r"(r[1]), "=r"(r[2]), "=r"(r[3]) : "r"(saddr));
}

// FMA-pipe exp for y <= 0 (rel err ~4e-5). Runs parallel to MUFU __expf.
__device__ __forceinline__ float fexp_poly(float y) {
    float t = fmaxf(y, -30.0f) * 1.4426950408889634f;   // log2 e
    float z = t + 12582912.0f;                           // RN round(t)
    int   i = __float_as_int(z);
    float f = t - (z - 12582912.0f);                     // f in [-0.5, 0.5]
    float p = 0.0096180f;                                // 2^f Taylor deg-4
    p = fmaf(p, f, 0.0555041f);
    p = fmaf(p, f, 0.2402265f);
    p = fmaf(p, f, 0.6931472f);
    p = fmaf(p, f, 1.0f);
    float s = __int_as_float((i - 1262485377) << 23);    // 2^round(t)
    return p * s;
}

// ---------------------------------------------------------------------------
// fp16 tensor-core GEMM (unchanged from Round 13 — 413/140 us)
// ---------------------------------------------------------------------------
#define SA 40
#define SB 136
#define ABUF_B (128 * SA * 2)
#define BBUF_B (32 * SB * 2)
#define GEMM_SMEM_BYTES (2 * ABUF_B + 2 * BBUF_B)   // 37888

__global__ __launch_bounds__(256, 2) void gemm_fp16(const float* __restrict__ Ap,
                                                    const float* __restrict__ B,
                                                    float* __restrict__ Cp,
                                                    int M, int Nc, int K, int mode)
{
    const float* A = (mode == 0) ? Ap : g_att;
    float*       C = (mode == 0) ? g_qkv : Cp;

    extern __shared__ char dsm[];
    const uint32_t sbase = (uint32_t)__cvta_generic_to_shared(dsm);

    const int tid  = threadIdx.x;
    const int row0 = blockIdx.y * 128;
    const int col0 = blockIdx.x * 128;
    const int wid  = tid >> 5;
    const int lane = tid & 31;
    const int g    = lane >> 2;
    const int tg   = lane & 3;
    const int wm   = (wid & 1) * 64;
    const int wn   = (wid >> 1) * 32;
    const int qd   = lane >> 3;
    const int rr   = lane & 7;

    const uint32_t a_off0 = (uint32_t)(((wm + (qd & 1) * 8 + rr) * SA + (qd >> 1) * 8) * 2);
    const uint32_t b_off0 = (uint32_t)((((qd & 1) * 8 + rr) * SB + wn + (qd >> 1) * 8) * 2);

    float acc[4][4][4];
#pragma unroll
    for (int mi = 0; mi < 4; mi++)
#pragma unroll
        for (int ni = 0; ni < 4; ni++)
#pragma unroll
            for (int r = 0; r < 4; r++) acc[mi][ni][r] = 0.f;

    const int arow = tid >> 3, acol = (tid & 7) * 4;
    const float* Ag = A + (size_t)(row0 + arow) * K + acol;
    const int brow = tid >> 5, bcol = (tid & 31) * 4;
    const float* Bg = B + (size_t)brow * Nc + col0 + bcol;

    float4 ra[4], rb[4];

    auto load_regs = [&](int kt) {
#pragma unroll
        for (int l = 0; l < 4; l++) {
            ra[l] = *(const float4*)(Ag + kt + (size_t)(32 * l) * K);
            rb[l] = *(const float4*)(Bg + (size_t)(kt + 8 * l) * Nc);
        }
    };

    auto store_tiles = [&](int buf) {
        char* As = dsm + buf * ABUF_B;
        char* Bs = dsm + 2 * ABUF_B + buf * BBUF_B;
#pragma unroll
        for (int l = 0; l < 4; l++) {
            uint2 av = make_uint2(pack_h2(ra[l].x, ra[l].y),
                                  pack_h2(ra[l].z, ra[l].w));
            *(uint2*)(As + ((arow + 32 * l) * SA + acol) * 2) = av;
            uint2 bv = make_uint2(pack_h2(rb[l].x, rb[l].y),
                                  pack_h2(rb[l].z, rb[l].w));
            *(uint2*)(Bs + ((brow + 8 * l) * SB + bcol) * 2) = bv;
        }
    };

    auto compute = [&](int buf) {
        const uint32_t ab = sbase + buf * ABUF_B + a_off0;
        const uint32_t bb = sbase + 2 * ABUF_B + buf * BBUF_B + b_off0;
#pragma unroll
        for (int ks = 0; ks < 2; ks++) {
            uint32_t bf[4][2];
            {
                uint32_t t0[4], t1[4];
                ldsm4t(t0, bb + ks * (16 * SB * 2));
                ldsm4t(t1, bb + ks * (16 * SB * 2) + 32);
                bf[0][0] = t0[0]; bf[0][1] = t0[1];
                bf[1][0] = t0[2]; bf[1][1] = t0[3];
                bf[2][0] = t1[0]; bf[2][1] = t1[1];
                bf[3][0] = t1[2]; bf[3][1] = t1[3];
            }
#pragma unroll
            for (int mi = 0; mi < 4; mi++) {
                uint32_t af[4];
                ldsm4(af, ab + mi * (16 * SA * 2) + ks * 32);
#pragma unroll
                for (int ni = 0; ni < 4; ni++)
                    mma_fp16(acc[mi][ni], af, bf[ni][0], bf[ni][1]);
            }
        }
    };

    load_regs(0);
    store_tiles(0);
    __syncthreads();

    int buf = 0;
    for (int kt = 0; kt < K; kt += 32) {
        const bool more = (kt + 32 < K);
        if (more) load_regs(kt + 32);
        compute(buf);
        if (more) {
            store_tiles(buf ^ 1);
            __syncthreads();
        }
        buf ^= 1;
    }

#pragma unroll
    for (int mi = 0; mi < 4; mi++) {
#pragma unroll
        for (int ni = 0; ni < 4; ni++) {
            const int row = row0 + wm + mi * 16;
            const int col = col0 + wn + ni * 8 + 2 * tg;
            float2 v01 = make_float2(acc[mi][ni][0], acc[mi][ni][1]);
            float2 v23 = make_float2(acc[mi][ni][2], acc[mi][ni][3]);
            *(float2*)&C[(size_t)(row + g    ) * Nc + col] = v01;
            *(float2*)&C[(size_t)(row + g + 8) * Nc + col] = v23;
        }
    }
}

// ---------------------------------------------------------------------------
// Flash attention (causal): fp16 mma (m16n8k16) + hybrid MUFU/poly exp.
// Grid (N/64, B*H), 128 threads = 4 warps; warp w owns rows [16w, 16w+16).
// Smem (halves): Qh[64][136] | Kh[64][136] | Vh[64][136] | Ph[64][72]
//   QK: A=Qh[m][k] via ldsm4; B=Kh[n][k] via ldsm4 (non-trans = col-major B).
//   PV: A=Ph[m][k] via ldsm4; B=Vh[k][n] via ldsm4t (GEMM-validated pattern).
// ---------------------------------------------------------------------------
#define SQ  136
#define SP  72
#define QH_B 0
#define KH_B (64 * SQ * 2)            // 17408
#define VH_B (2 * 64 * SQ * 2)        // 34816
#define PH_B (3 * 64 * SQ * 2)        // 52224
#define ATT_SMEM_BYTES (3 * 64 * SQ * 2 + 64 * SP * 2)   // 61440

__global__ __launch_bounds__(128, 3) void attn_mma()
{
    extern __shared__ char dsm[];
    const uint32_t sbase = (uint32_t)__cvta_generic_to_shared(dsm);

    const int bh  = blockIdx.y;
    const int b   = bh >> 4;
    const int h   = bh & 15;
    const int m0  = blockIdx.x * 64;
    const int tid = threadIdx.x;
    const int wid = tid >> 5;
    const int lane = tid & 31;
    const int g   = lane >> 2;
    const int tg  = lane & 3;
    const int qd  = lane >> 3;
    const int rr  = lane & 7;

    const int r0  = wid * 16 + g;
    const int r1  = r0 + 8;
    const int gr0 = m0 + r0;
    const int gr1 = m0 + r1;

    // ldmatrix lane-address bases
    const uint32_t qa_base = sbase + QH_B +
        ((wid * 16 + (qd & 1) * 8 + rr) * SQ + (qd >> 1) * 8) * 2;
    const uint32_t kb_base = sbase + KH_B +
        (((qd >> 1) * 8 + rr) * SQ + (qd & 1) * 8) * 2;
    const uint32_t vb_base = sbase + VH_B +
        (((qd & 1) * 8 + rr) * SQ + (qd >> 1) * 8) * 2;
    const uint32_t pa_base = sbase + PH_B +
        ((wid * 16 + (qd & 1) * 8 + rr) * SP + (qd >> 1) * 8) * 2;

    // ---- Load Q [64 x 128], scaled, fp16 ----
    const float* Qg = g_qkv + ((size_t)(b * NN + m0)) * TDI + h * DD;
#pragma unroll
    for (int l = 0; l < 16; l++) {
        int fl = tid + l * 128;
        int r  = fl >> 5;
        int d4 = (fl & 31) * 4;
        float4 v = *(const float4*)(Qg + (size_t)r * TDI + d4);
        *(uint2*)(dsm + QH_B + (r * SQ + d4) * 2) =
            make_uint2(pack_h2(v.x * QK_SCALE, v.y * QK_SCALE),
                       pack_h2(v.z * QK_SCALE, v.w * QK_SCALE));
    }

    float m_r[2] = {-1e30f, -1e30f};
    float l_r[2] = {0.f, 0.f};
    float O[16][4];
#pragma unroll
    for (int ni = 0; ni < 16; ni++)
#pragma unroll
        for (int r = 0; r < 4; r++) O[ni][r] = 0.f;

    const int ntiles = blockIdx.x + 1;
    for (int t = 0; t < ntiles; t++) {
        const int k0 = t * 64;
        __syncthreads();   // prior K/V reads complete

        // ---- Load K tile (keys x d) and V tile (keys x d), fp16 ----
        const float* Kg = g_qkv + ((size_t)(b * NN + k0)) * TDI + DI + h * DD;
        const float* Vg = Kg + DI;
#pragma unroll
        for (int l = 0; l < 16; l++) {
            int fl = tid + l * 128;
            int r  = fl >> 5;
            int d4 = (fl & 31) * 4;
            float4 kv = *(const float4*)(Kg + (size_t)r * TDI + d4);
            *(uint2*)(dsm + KH_B + (r * SQ + d4) * 2) =
                make_uint2(pack_h2(kv.x, kv.y), pack_h2(kv.z, kv.w));
            float4 vv = *(const float4*)(Vg + (size_t)r * TDI + d4);
            *(uint2*)(dsm + VH_B + (r * SQ + d4) * 2) =
                make_uint2(pack_h2(vv.x, vv.y), pack_h2(vv.z, vv.w));
        }
        __syncthreads();

        // ---- S = Q @ K^T  (8 k16-steps over d=128) ----
        float S[8][4];
#pragma unroll
        for (int ni = 0; ni < 8; ni++)
#pragma unroll
            for (int r = 0; r < 4; r++) S[ni][r] = 0.f;

#pragma unroll
        for (int ks = 0; ks < 8; ks++) {
            uint32_t af[4];
            ldsm4(af, qa_base + ks * 32);
#pragma unroll
            for (int pr = 0; pr < 4; pr++) {
                uint32_t bt[4];
                ldsm4(bt, kb_base + pr * (16 * SQ * 2) + ks * 32);
                mma_fp16(S[2 * pr    ], af, bt[0], bt[1]);
                mma_fp16(S[2 * pr + 1], af, bt[2], bt[3]);
            }
        }

        // ---- Causal mask (diagonal tile only) ----
        if (t == ntiles - 1) {
#pragma unroll
            for (int ni = 0; ni < 8; ni++) {
                const int c = k0 + ni * 8 + 2 * tg;
                if (c     > gr0) S[ni][0] = -1e30f;
                if (c + 1 > gr0) S[ni][1] = -1e30f;
                if (c     > gr1) S[ni][2] = -1e30f;
                if (c + 1 > gr1) S[ni][3] = -1e30f;
            }
        }

        // ---- Softmax: hybrid MUFU / FMA-poly exp ----
        float mx0 = -1e30f, mx1 = -1e30f;
#pragma unroll
        for (int ni = 0; ni < 8; ni++) {
            mx0 = fmaxf(mx0, fmaxf(S[ni][0], S[ni][1]));
            mx1 = fmaxf(mx1, fmaxf(S[ni][2], S[ni][3]));
        }
        mx0 = fmaxf(mx0, __shfl_xor_sync(0xffffffffu, mx0, 1));
        mx0 = fmaxf(mx0, __shfl_xor_sync(0xffffffffu, mx0, 2));
        mx1 = fmaxf(mx1, __shfl_xor_sync(0xffffffffu, mx1, 1));
        mx1 = fmaxf(mx1, __shfl_xor_sync(0xffffffffu, mx1, 2));

        const float mn0 = fmaxf(m_r[0], mx0);
        const float mn1 = fmaxf(m_r[1], mx1);
        const float sc0 = __expf(m_r[0] - mn0);
        const float sc1 = __expf(m_r[1] - mn1);

        float sum0 = 0.f, sum1 = 0.f;
        char* p0 = dsm + PH_B + (r0 * SP + 2 * tg) * 2;
        char* p1 = dsm + PH_B + (r1 * SP + 2 * tg) * 2;
#pragma unroll
        for (int ni = 0; ni < 8; ni++) {
            float p00, p01, p10, p11;
            if (ni & 1) {                       // FMA-pipe polynomial
                p00 = fexp_poly(S[ni][0] - mn0);
                p01 = fexp_poly(S[ni][1] - mn0);
                p10 = fexp_poly(S[ni][2] - mn1);
                p11 = fexp_poly(S[ni][3] - mn1);
            } else {                            // MUFU
                p00 = __expf(S[ni][0] - mn0);
                p01 = __expf(S[ni][1] - mn0);
                p10 = __expf(S[ni][2] - mn1);
                p11 = __expf(S[ni][3] - mn1);
            }
            sum0 += p00 + p01;
            sum1 += p10 + p11;
            *(uint32_t*)(p0 + ni * 16) = pack_h2(p00, p01);
            *(uint32_t*)(p1 + ni * 16) = pack_h2(p10, p11);
        }
        sum0 += __shfl_xor_sync(0xffffffffu, sum0, 1);
        sum0 += __shfl_xor_sync(0xffffffffu, sum0, 2);
        sum1 += __shfl_xor_sync(0xffffffffu, sum1, 1);
        sum1 += __shfl_xor_sync(0xffffffffu, sum1, 2);

        l_r[0] = l_r[0] * sc0 + sum0;  m_r[0] = mn0;
        l_r[1] = l_r[1] * sc1 + sum1;  m_r[1] = mn1;

#pragma unroll
        for (int ni = 0; ni < 16; ni++) {
            O[ni][0] *= sc0; O[ni][1] *= sc0;
            O[ni][2] *= sc1; O[ni][3] *= sc1;
        }
        __syncwarp();   // P visible to warp's ldmatrix

        // ---- O += P @ V  (4 k16-steps over 64 keys) ----
#pragma unroll
        for (int ks = 0; ks < 4; ks++) {
            uint32_t af[4];
            ldsm4(af, pa_base + ks * 32);
#pragma unroll
            for (int pr = 0; pr < 8; pr++) {
                uint32_t bt[4];
                ldsm4t(bt, vb_base + pr * 32 + ks * (16 * SQ * 2));
                mma_fp16(O[2 * pr    ], af, bt[0], bt[1]);
                mma_fp16(O[2 * pr + 1], af, bt[2], bt[3]);
            }
        }
    }

    // ---- Epilogue ----
    const float inv0 = 1.0f / l_r[0];
    const float inv1 = 1.0f / l_r[1];
    float* O0 = g_att + ((size_t)(b * NN + gr0)) * DI + h * DD;
    float* O1 = g_att + ((size_t)(b * NN + gr1)) * DI + h * DD;
#pragma unroll
    for (int ni = 0; ni < 16; ni++) {
        const int c = ni * 8 + 2 * tg;
        *(float2*)&O0[c] = make_float2(O[ni][0] * inv0, O[ni][1] * inv0);
        *(float2*)&O1[c] = make_float2(O[ni][2] * inv1, O[ni][3] * inv1);
    }
}

// ---------------------------------------------------------------------------
// Launch
// ---------------------------------------------------------------------------
extern "C" void kernel_launch(void* const* d_in, const int* in_sizes, int n_in,
                              void* d_out, int out_size)
{
    const float* x     = (const float*)d_in[0];   // [2, 2048, 2048]
    const float* w_qkv = (const float*)d_in[1];   // [2048, 6144]
    const float* w_out = (const float*)d_in[2];   // [2048, 2048]
    float* out = (float*)d_out;                   // [2, 2048, 2048]

    cudaFuncSetAttribute(gemm_fp16,
                         cudaFuncAttributeMaxDynamicSharedMemorySize,
                         GEMM_SMEM_BYTES);
    cudaFuncSetAttribute(attn_mma,
                         cudaFuncAttributeMaxDynamicSharedMemorySize,
                         ATT_SMEM_BYTES);

    // 1) QKV projection: [4096, 2048] @ [2048, 6144]  -> g_qkv
    gemm_fp16<<<dim3(TDI / 128, (BB * NN) / 128), 256, GEMM_SMEM_BYTES>>>(
        x, w_qkv, nullptr, BB * NN, TDI, DIMM, 0);

    // 2) Causal flash attention (fp16 MMA + hybrid exp): g_qkv -> g_att
    attn_mma<<<dim3(NN / 64, BB * HH), 128, ATT_SMEM_BYTES>>>();

    // 3) Output projection: [4096, 2048] @ [2048, 2048]  g_att -> out
    gemm_fp16<<<dim3(DIMM / 128, (BB * NN) / 128), 256, GEMM_SMEM_BYTES>>>(
        nullptr, w_out, out, BB * NN, DIMM, DIMM, 1);
}

// round 15
// speedup vs baseline: 7.7292x; 1.2033x over previous
#include <cuda_runtime.h>
#include <cuda_fp16.h>
#include <cstdint>
#include <cstddef>

// Problem constants
#define BB   2
#define NN   2048
#define DIMM 2048
#define HH   16
#define DD   128
#define DI   2048          // HEADS * DIM_HEAD
#define TDI  6144          // 3 * DI
#define QK_SCALE 0.08838834764831845f  // 128^-0.5

#define NX  ((size_t)BB * NN * DIMM)   // x elems
#define NW1 ((size_t)DIMM * TDI)       // w_qkv elems
#define NW2 ((size_t)DI * DIMM)        // w_out elems

// fp16 scratch
__device__ __half g_xh  [NX];                  // 16 MB
__device__ __half g_wqh [NW1];                 // 24 MB
__device__ __half g_woh [NW2];                 // 8 MB
__device__ __half g_qkvh[(size_t)BB * NN * TDI]; // 48 MB
__device__ __half g_atth[(size_t)BB * NN * DI];  // 16 MB

// ---------------------------------------------------------------------------
// helpers
// ---------------------------------------------------------------------------
__device__ __forceinline__ uint32_t pack_h2(float lo, float hi) {
    __half2 h = __floats2half2_rn(lo, hi);
    return *reinterpret_cast<uint32_t*>(&h);
}

__device__ __forceinline__ void mma_fp16(float c[4],
                                         const uint32_t a[4],
                                         const uint32_t b0, const uint32_t b1) {
    asm volatile(
        "mma.sync.aligned.m16n8k16.row.col.f32.f16.f16.f32 "
        "{%0,%1,%2,%3}, {%4,%5,%6,%7}, {%8,%9}, {%0,%1,%2,%3};"
        : "+f"(c[0]), "+f"(c[1]), "+f"(c[2]), "+f"(c[3])
        : "r"(a[0]), "r"(a[1]), "r"(a[2]), "r"(a[3]),
          "r"(b0), "r"(b1));
}

__device__ __forceinline__ void ldsm4(uint32_t r[4], uint32_t saddr) {
    asm volatile("ldmatrix.sync.aligned.m8n8.x4.shared.b16 {%0,%1,%2,%3}, [%4];"
        : "=r"(r[0]), "=r"(r[1]), "=r"(r[2]), "=r"(r[3]) : "r"(saddr));
}

__device__ __forceinline__ void ldsm4t(uint32_t r[4], uint32_t saddr) {
    asm volatile("ldmatrix.sync.aligned.m8n8.x4.trans.shared.b16 {%0,%1,%2,%3}, [%4];"
        : "=r"(r[0]), "=r"(r[1]), "=r"(r[2]), "=r"(r[3]) : "r"(saddr));
}

__device__ __forceinline__ void cp16(uint32_t smem_dst, const void* gptr) {
    asm volatile("cp.async.cg.shared.global [%0], [%1], 16;"
                 :: "r"(smem_dst), "l"(gptr) : "memory");
}
#define CP_COMMIT() asm volatile("cp.async.commit_group;" ::: "memory")
#define CP_WAIT0()  asm volatile("cp.async.wait_group 0;" ::: "memory")

// FMA-pipe exp for y <= 0 (rel err ~4e-5). Runs parallel to MUFU __expf.
__device__ __forceinline__ float fexp_poly(float y) {
    float t = fmaxf(y, -30.0f) * 1.4426950408889634f;
    float z = t + 12582912.0f;
    int   i = __float_as_int(z);
    float f = t - (z - 12582912.0f);
    float p = 0.0096180f;
    p = fmaf(p, f, 0.0555041f);
    p = fmaf(p, f, 0.2402265f);
    p = fmaf(p, f, 0.6931472f);
    p = fmaf(p, f, 1.0f);
    float s = __int_as_float((i - 1262485377) << 23);
    return p * s;
}

// ---------------------------------------------------------------------------
// Pre-convert: fp32 inputs -> fp16 scratch (one streaming pass)
// ---------------------------------------------------------------------------
__global__ __launch_bounds__(256) void convert_fp16(const float* __restrict__ x,
                                                    const float* __restrict__ w1,
                                                    const float* __restrict__ w2)
{
    const size_t idx = (size_t)blockIdx.x * blockDim.x + threadIdx.x;
    const size_t stride = (size_t)gridDim.x * blockDim.x;

    for (size_t i = idx; i < NX / 4; i += stride) {
        float4 v = ((const float4*)x)[i];
        ((uint2*)g_xh)[i] = make_uint2(pack_h2(v.x, v.y), pack_h2(v.z, v.w));
    }
    for (size_t i = idx; i < NW1 / 4; i += stride) {
        float4 v = ((const float4*)w1)[i];
        ((uint2*)g_wqh)[i] = make_uint2(pack_h2(v.x, v.y), pack_h2(v.z, v.w));
    }
    for (size_t i = idx; i < NW2 / 4; i += stride) {
        float4 v = ((const float4*)w2)[i];
        ((uint2*)g_woh)[i] = make_uint2(pack_h2(v.x, v.y), pack_h2(v.z, v.w));
    }
}

// ---------------------------------------------------------------------------
// fp16 GEMM with cp.async operand staging.
// C[M,Nc] = A[M,K] @ B[K,Nc]; A,B fp16 in gmem. Block 128x128, BK=32,
// 256 threads = 8 warps (2m x 4n). Per iter per thread: 4 cp.async.16B.
// mode 0: A=g_xh,  B=g_wqh, C=g_qkvh (fp16; QK_SCALE folded for col0<DI)
// mode 1: A=g_atth,B=g_woh, C=Cp (fp32 out)
// ---------------------------------------------------------------------------
#define SA 40
#define SB 136
#define ABUF_B (128 * SA * 2)        // 10240
#define BBUF_B (32 * SB * 2)         // 8704
#define GEMM_SMEM_BYTES (2 * ABUF_B + 2 * BBUF_B)   // 37888

__global__ __launch_bounds__(256, 2) void gemm_fp16(float* __restrict__ Cp,
                                                    int M, int Nc, int K, int mode)
{
    const __half* A  = (mode == 0) ? g_xh  : g_atth;
    const __half* Bh = (mode == 0) ? g_wqh : g_woh;

    extern __shared__ char dsm[];
    const uint32_t sbase = (uint32_t)__cvta_generic_to_shared(dsm);

    const int tid  = threadIdx.x;
    const int row0 = blockIdx.y * 128;
    const int col0 = blockIdx.x * 128;
    const int wid  = tid >> 5;
    const int lane = tid & 31;
    const int g    = lane >> 2;
    const int tg   = lane & 3;
    const int wm   = (wid & 1) * 64;
    const int wn   = (wid >> 1) * 32;
    const int qd   = lane >> 3;
    const int rr   = lane & 7;

    const uint32_t a_off0 = (uint32_t)(((wm + (qd & 1) * 8 + rr) * SA + (qd >> 1) * 8) * 2);
    const uint32_t b_off0 = (uint32_t)((((qd & 1) * 8 + rr) * SB + wn + (qd >> 1) * 8) * 2);

    float acc[4][4][4];
#pragma unroll
    for (int mi = 0; mi < 4; mi++)
#pragma unroll
        for (int ni = 0; ni < 4; ni++)
#pragma unroll
            for (int r = 0; r < 4; r++) acc[mi][ni][r] = 0.f;

    // cp.async seg mapping: A 512 segs (row=s>>2, sc=s&3), B 512 (row=s>>4, sc=s&15)
    const int a_r0 = tid >> 2,          a_c0 = (tid & 3) * 8;
    const int a_r1 = (tid + 256) >> 2,  a_c1 = a_c0;
    const int b_r0 = tid >> 4,          b_c0 = (tid & 15) * 8;
    const int b_r1 = (tid + 256) >> 4,  b_c1 = b_c0;

    const uint32_t dA0 = sbase + (a_r0 * SA + a_c0) * 2;
    const uint32_t dA1 = sbase + (a_r1 * SA + a_c1) * 2;
    const uint32_t dB0 = sbase + 2 * ABUF_B + (b_r0 * SB + b_c0) * 2;
    const uint32_t dB1 = sbase + 2 * ABUF_B + (b_r1 * SB + b_c1) * 2;

    const __half* sA0 = A + (size_t)(row0 + a_r0) * K + a_c0;
    const __half* sA1 = A + (size_t)(row0 + a_r1) * K + a_c1;
    const __half* sB0 = Bh + (size_t)b_r0 * Nc + col0 + b_c0;
    const __half* sB1 = Bh + (size_t)b_r1 * Nc + col0 + b_c1;

    auto issue_loads = [&](int kt, int buf) {
        cp16(dA0 + buf * ABUF_B, sA0 + kt);
        cp16(dA1 + buf * ABUF_B, sA1 + kt);
        cp16(dB0 + buf * BBUF_B, sB0 + (size_t)kt * Nc);
        cp16(dB1 + buf * BBUF_B, sB1 + (size_t)kt * Nc);
        CP_COMMIT();
    };

    auto compute = [&](int buf) {
        const uint32_t ab = sbase + buf * ABUF_B + a_off0;
        const uint32_t bb = sbase + 2 * ABUF_B + buf * BBUF_B + b_off0;
#pragma unroll
        for (int ks = 0; ks < 2; ks++) {
            uint32_t bf[4][2];
            {
                uint32_t t0[4], t1[4];
                ldsm4t(t0, bb + ks * (16 * SB * 2));
                ldsm4t(t1, bb + ks * (16 * SB * 2) + 32);
                bf[0][0] = t0[0]; bf[0][1] = t0[1];
                bf[1][0] = t0[2]; bf[1][1] = t0[3];
                bf[2][0] = t1[0]; bf[2][1] = t1[1];
                bf[3][0] = t1[2]; bf[3][1] = t1[3];
            }
#pragma unroll
            for (int mi = 0; mi < 4; mi++) {
                uint32_t af[4];
                ldsm4(af, ab + mi * (16 * SA * 2) + ks * 32);
#pragma unroll
                for (int ni = 0; ni < 4; ni++)
                    mma_fp16(acc[mi][ni], af, bf[ni][0], bf[ni][1]);
            }
        }
    };

    issue_loads(0, 0);

    int buf = 0;
    for (int kt = 0; kt < K; kt += 32) {
        CP_WAIT0();
        __syncthreads();
        if (kt + 32 < K) issue_loads(kt + 32, buf ^ 1);
        compute(buf);
        buf ^= 1;
    }

    // Epilogue
    if (mode == 0) {
        const float sc = (col0 < DI) ? QK_SCALE : 1.0f;   // fold Q scaling
        __half* C = g_qkvh;
#pragma unroll
        for (int mi = 0; mi < 4; mi++) {
#pragma unroll
            for (int ni = 0; ni < 4; ni++) {
                const int row = row0 + wm + mi * 16;
                const int col = col0 + wn + ni * 8 + 2 * tg;
                *(uint32_t*)&C[(size_t)(row + g    ) * Nc + col] =
                    pack_h2(acc[mi][ni][0] * sc, acc[mi][ni][1] * sc);
                *(uint32_t*)&C[(size_t)(row + g + 8) * Nc + col] =
                    pack_h2(acc[mi][ni][2] * sc, acc[mi][ni][3] * sc);
            }
        }
    } else {
#pragma unroll
        for (int mi = 0; mi < 4; mi++) {
#pragma unroll
            for (int ni = 0; ni < 4; ni++) {
                const int row = row0 + wm + mi * 16;
                const int col = col0 + wn + ni * 8 + 2 * tg;
                *(float2*)&Cp[(size_t)(row + g    ) * Nc + col] =
                    make_float2(acc[mi][ni][0], acc[mi][ni][1]);
                *(float2*)&Cp[(size_t)(row + g + 8) * Nc + col] =
                    make_float2(acc[mi][ni][2], acc[mi][ni][3]);
            }
        }
    }
}

// ---------------------------------------------------------------------------
// Flash attention (causal): fp16 in/out, fp16 mma, hybrid MUFU/poly exp.
// Reads g_qkvh (Q pre-scaled by GEMM1), writes g_atth.
// Smem (halves): Qh[64][136] | Kh[64][136] | Vh[64][136] | Ph[64][72]
// ---------------------------------------------------------------------------
#define SQ  136
#define SP  72
#define QH_B 0
#define KH_B (64 * SQ * 2)
#define VH_B (2 * 64 * SQ * 2)
#define PH_B (3 * 64 * SQ * 2)
#define ATT_SMEM_BYTES (3 * 64 * SQ * 2 + 64 * SP * 2)   // 61440

__global__ __launch_bounds__(128, 3) void attn_mma()
{
    extern __shared__ char dsm[];
    const uint32_t sbase = (uint32_t)__cvta_generic_to_shared(dsm);

    const int bh  = blockIdx.y;
    const int b   = bh >> 4;
    const int h   = bh & 15;
    const int m0  = blockIdx.x * 64;
    const int tid = threadIdx.x;
    const int wid = tid >> 5;
    const int lane = tid & 31;
    const int g   = lane >> 2;
    const int tg  = lane & 3;
    const int qd  = lane >> 3;
    const int rr  = lane & 7;

    const int r0  = wid * 16 + g;
    const int r1  = r0 + 8;
    const int gr0 = m0 + r0;
    const int gr1 = m0 + r1;

    const uint32_t qa_base = sbase + QH_B +
        ((wid * 16 + (qd & 1) * 8 + rr) * SQ + (qd >> 1) * 8) * 2;
    const uint32_t kb_base = sbase + KH_B +
        (((qd >> 1) * 8 + rr) * SQ + (qd & 1) * 8) * 2;
    const uint32_t vb_base = sbase + VH_B +
        (((qd & 1) * 8 + rr) * SQ + (qd >> 1) * 8) * 2;
    const uint32_t pa_base = sbase + PH_B +
        ((wid * 16 + (qd & 1) * 8 + rr) * SP + (qd >> 1) * 8) * 2;

    // ---- Load Q [64 x 128] fp16 verbatim (already scaled) ----
    const __half* Qg = g_qkvh + ((size_t)(b * NN + m0)) * TDI + h * DD;
#pragma unroll
    for (int l = 0; l < 8; l++) {
        int fl = tid + l * 128;        // 1024 16B segs
        int r  = fl >> 4;
        int d8 = (fl & 15) * 8;
        *(uint4*)(dsm + QH_B + (r * SQ + d8) * 2) =
            *(const uint4*)(Qg + (size_t)r * TDI + d8);
    }

    float m_r[2] = {-1e30f, -1e30f};
    float l_r[2] = {0.f, 0.f};
    float O[16][4];
#pragma unroll
    for (int ni = 0; ni < 16; ni++)
#pragma unroll
        for (int r = 0; r < 4; r++) O[ni][r] = 0.f;

    const int ntiles = blockIdx.x + 1;
    for (int t = 0; t < ntiles; t++) {
        const int k0 = t * 64;
        __syncthreads();

        const __half* Kg = g_qkvh + ((size_t)(b * NN + k0)) * TDI + DI + h * DD;
        const __half* Vg = Kg + DI;
#pragma unroll
        for (int l = 0; l < 8; l++) {
            int fl = tid + l * 128;
            int r  = fl >> 4;
            int d8 = (fl & 15) * 8;
            *(uint4*)(dsm + KH_B + (r * SQ + d8) * 2) =
                *(const uint4*)(Kg + (size_t)r * TDI + d8);
            *(uint4*)(dsm + VH_B + (r * SQ + d8) * 2) =
                *(const uint4*)(Vg + (size_t)r * TDI + d8);
        }
        __syncthreads();

        // ---- S = Q @ K^T ----
        float S[8][4];
#pragma unroll
        for (int ni = 0; ni < 8; ni++)
#pragma unroll
            for (int r = 0; r < 4; r++) S[ni][r] = 0.f;

#pragma unroll
        for (int ks = 0; ks < 8; ks++) {
            uint32_t af[4];
            ldsm4(af, qa_base + ks * 32);
#pragma unroll
            for (int pr = 0; pr < 4; pr++) {
                uint32_t bt[4];
                ldsm4(bt, kb_base + pr * (16 * SQ * 2) + ks * 32);
                mma_fp16(S[2 * pr    ], af, bt[0], bt[1]);
                mma_fp16(S[2 * pr + 1], af, bt[2], bt[3]);
            }
        }

        if (t == ntiles - 1) {
#pragma unroll
            for (int ni = 0; ni < 8; ni++) {
                const int c = k0 + ni * 8 + 2 * tg;
                if (c     > gr0) S[ni][0] = -1e30f;
                if (c + 1 > gr0) S[ni][1] = -1e30f;
                if (c     > gr1) S[ni][2] = -1e30f;
                if (c + 1 > gr1) S[ni][3] = -1e30f;
            }
        }

        // ---- Softmax (hybrid exp) ----
        float mx0 = -1e30f, mx1 = -1e30f;
#pragma unroll
        for (int ni = 0; ni < 8; ni++) {
            mx0 = fmaxf(mx0, fmaxf(S[ni][0], S[ni][1]));
            mx1 = fmaxf(mx1, fmaxf(S[ni][2], S[ni][3]));
        }
        mx0 = fmaxf(mx0, __shfl_xor_sync(0xffffffffu, mx0, 1));
        mx0 = fmaxf(mx0, __shfl_xor_sync(0xffffffffu, mx0, 2));
        mx1 = fmaxf(mx1, __shfl_xor_sync(0xffffffffu, mx1, 1));
        mx1 = fmaxf(mx1, __shfl_xor_sync(0xffffffffu, mx1, 2));

        const float mn0 = fmaxf(m_r[0], mx0);
        const float mn1 = fmaxf(m_r[1], mx1);
        const float sc0 = __expf(m_r[0] - mn0);
        const float sc1 = __expf(m_r[1] - mn1);

        float sum0 = 0.f, sum1 = 0.f;
        char* p0 = dsm + PH_B + (r0 * SP + 2 * tg) * 2;
        char* p1 = dsm + PH_B + (r1 * SP + 2 * tg) * 2;
#pragma unroll
        for (int ni = 0; ni < 8; ni++) {
            float p00, p01, p10, p11;
            if (ni & 1) {
                p00 = fexp_poly(S[ni][0] - mn0);
                p01 = fexp_poly(S[ni][1] - mn0);
                p10 = fexp_poly(S[ni][2] - mn1);
                p11 = fexp_poly(S[ni][3] - mn1);
            } else {
                p00 = __expf(S[ni][0] - mn0);
                p01 = __expf(S[ni][1] - mn0);
                p10 = __expf(S[ni][2] - mn1);
                p11 = __expf(S[ni][3] - mn1);
            }
            sum0 += p00 + p01;
            sum1 += p10 + p11;
            *(uint32_t*)(p0 + ni * 16) = pack_h2(p00, p01);
            *(uint32_t*)(p1 + ni * 16) = pack_h2(p10, p11);
        }
        sum0 += __shfl_xor_sync(0xffffffffu, sum0, 1);
        sum0 += __shfl_xor_sync(0xffffffffu, sum0, 2);
        sum1 += __shfl_xor_sync(0xffffffffu, sum1, 1);
        sum1 += __shfl_xor_sync(0xffffffffu, sum1, 2);

        l_r[0] = l_r[0] * sc0 + sum0;  m_r[0] = mn0;
        l_r[1] = l_r[1] * sc1 + sum1;  m_r[1] = mn1;

#pragma unroll
        for (int ni = 0; ni < 16; ni++) {
            O[ni][0] *= sc0; O[ni][1] *= sc0;
            O[ni][2] *= sc1; O[ni][3] *= sc1;
        }
        __syncwarp();

        // ---- O += P @ V ----
#pragma unroll
        for (int ks = 0; ks < 4; ks++) {
            uint32_t af[4];
            ldsm4(af, pa_base + ks * 32);
#pragma unroll
            for (int pr = 0; pr < 8; pr++) {
                uint32_t bt[4];
                ldsm4t(bt, vb_base + pr * 32 + ks * (16 * SQ * 2));
                mma_fp16(O[2 * pr    ], af, bt[0], bt[1]);
                mma_fp16(O[2 * pr + 1], af, bt[2], bt[3]);
            }
        }
    }

    // ---- Epilogue: normalize, write fp16 ----
    const float inv0 = 1.0f / l_r[0];
    const float inv1 = 1.0f / l_r[1];
    __half* O0 = g_atth + ((size_t)(b * NN + gr0)) * DI + h * DD;
    __half* O1 = g_atth + ((size_t)(b * NN + gr1)) * DI + h * DD;
#pragma unroll
    for (int ni = 0; ni < 16; ni++) {
        const int c = ni * 8 + 2 * tg;
        *(uint32_t*)&O0[c] = pack_h2(O[ni][0] * inv0, O[ni][1] * inv0);
        *(uint32_t*)&O1[c] = pack_h2(O[ni][2] * inv1, O[ni][3] * inv1);
    }
}

// ---------------------------------------------------------------------------
// Launch
// ---------------------------------------------------------------------------
extern "C" void kernel_launch(void* const* d_in, const int* in_sizes, int n_in,
                              void* d_out, int out_size)
{
    const float* x     = (const float*)d_in[0];   // [2, 2048, 2048]
    const float* w_qkv = (const float*)d_in[1];   // [2048, 6144]
    const float* w_out = (const float*)d_in[2];   // [2048, 2048]
    float* out = (float*)d_out;                   // [2, 2048, 2048]

    cudaFuncSetAttribute(gemm_fp16,
                         cudaFuncAttributeMaxDynamicSharedMemorySize,
                         GEMM_SMEM_BYTES);
    cudaFuncSetAttribute(attn_mma,
                         cudaFuncAttributeMaxDynamicSharedMemorySize,
                         ATT_SMEM_BYTES);

    // 0) fp32 -> fp16 conversion of inputs
    convert_fp16<<<592, 256>>>(x, w_qkv, w_out);

    // 1) QKV projection -> g_qkvh (fp16, Q pre-scaled)
    gemm_fp16<<<dim3(TDI / 128, (BB * NN) / 128), 256, GEMM_SMEM_BYTES>>>(
        nullptr, BB * NN, TDI, DIMM, 0);

    // 2) Causal flash attention: g_qkvh -> g_atth
    attn_mma<<<dim3(NN / 64, BB * HH), 128, ATT_SMEM_BYTES>>>();

    // 3) Output projection: g_atth @ g_woh -> out (fp32)
    gemm_fp16<<<dim3(DIMM / 128, (BB * NN) / 128), 256, GEMM_SMEM_BYTES>>>(
        out, BB * NN, DIMM, DIMM, 1);
}

// round 16
// speedup vs baseline: 8.3665x; 1.0825x over previous
#include <cuda_runtime.h>
#include <cuda_fp16.h>
#include <cstdint>
#include <cstddef>

// Problem constants
#define BB   2
#define NN   2048
#define DIMM 2048
#define HH   16
#define DD   128
#define DI   2048          // HEADS * DIM_HEAD
#define TDI  6144          // 3 * DI
#define QK_SCALE 0.08838834764831845f  // 128^-0.5

#define NX  ((size_t)BB * NN * DIMM)   // x elems
#define NW1 ((size_t)DIMM * TDI)       // w_qkv elems
#define NW2 ((size_t)DI * DIMM)        // w_out elems

// fp16 scratch
__device__ __half g_xh  [NX];
__device__ __half g_wqh [NW1];
__device__ __half g_woh [NW2];
__device__ __half g_qkvh[(size_t)BB * NN * TDI];
__device__ __half g_atth[(size_t)BB * NN * DI];

// ---------------------------------------------------------------------------
// helpers
// ---------------------------------------------------------------------------
__device__ __forceinline__ uint32_t pack_h2(float lo, float hi) {
    __half2 h = __floats2half2_rn(lo, hi);
    return *reinterpret_cast<uint32_t*>(&h);
}

__device__ __forceinline__ void mma_fp16(float c[4],
                                         const uint32_t a[4],
                                         const uint32_t b0, const uint32_t b1) {
    asm volatile(
        "mma.sync.aligned.m16n8k16.row.col.f32.f16.f16.f32 "
        "{%0,%1,%2,%3}, {%4,%5,%6,%7}, {%8,%9}, {%0,%1,%2,%3};"
        : "+f"(c[0]), "+f"(c[1]), "+f"(c[2]), "+f"(c[3])
        : "r"(a[0]), "r"(a[1]), "r"(a[2]), "r"(a[3]),
          "r"(b0), "r"(b1));
}

__device__ __forceinline__ void ldsm4(uint32_t r[4], uint32_t saddr) {
    asm volatile("ldmatrix.sync.aligned.m8n8.x4.shared.b16 {%0,%1,%2,%3}, [%4];"
        : "=r"(r[0]), "=r"(r[1]), "=r"(r[2]), "=r"(r[3]) : "r"(saddr));
}

__device__ __forceinline__ void ldsm4t(uint32_t r[4], uint32_t saddr) {
    asm volatile("ldmatrix.sync.aligned.m8n8.x4.trans.shared.b16 {%0,%1,%2,%3}, [%4];"
        : "=r"(r[0]), "=r"(r[1]), "=r"(r[2]), "=r"(r[3]) : "r"(saddr));
}

__device__ __forceinline__ void cp16(uint32_t smem_dst, const void* gptr) {
    asm volatile("cp.async.cg.shared.global [%0], [%1], 16;"
                 :: "r"(smem_dst), "l"(gptr) : "memory");
}
#define CP_COMMIT() asm volatile("cp.async.commit_group;" ::: "memory")
#define CP_WAIT0()  asm volatile("cp.async.wait_group 0;" ::: "memory")

// FMA-pipe exp for y <= 0 (rel err ~4e-5). Runs parallel to MUFU __expf.
__device__ __forceinline__ float fexp_poly(float y) {
    float t = fmaxf(y, -30.0f) * 1.4426950408889634f;
    float z = t + 12582912.0f;
    int   i = __float_as_int(z);
    float f = t - (z - 12582912.0f);
    float p = 0.0096180f;
    p = fmaf(p, f, 0.0555041f);
    p = fmaf(p, f, 0.2402265f);
    p = fmaf(p, f, 0.6931472f);
    p = fmaf(p, f, 1.0f);
    float s = __int_as_float((i - 1262485377) << 23);
    return p * s;
}

// ---------------------------------------------------------------------------
// Pre-convert: fp32 inputs -> fp16 scratch (one streaming pass)
// ---------------------------------------------------------------------------
__global__ __launch_bounds__(256) void convert_fp16(const float* __restrict__ x,
                                                    const float* __restrict__ w1,
                                                    const float* __restrict__ w2)
{
    const size_t idx = (size_t)blockIdx.x * blockDim.x + threadIdx.x;
    const size_t stride = (size_t)gridDim.x * blockDim.x;

    for (size_t i = idx; i < NX / 4; i += stride) {
        float4 v = ((const float4*)x)[i];
        ((uint2*)g_xh)[i] = make_uint2(pack_h2(v.x, v.y), pack_h2(v.z, v.w));
    }
    for (size_t i = idx; i < NW1 / 4; i += stride) {
        float4 v = ((const float4*)w1)[i];
        ((uint2*)g_wqh)[i] = make_uint2(pack_h2(v.x, v.y), pack_h2(v.z, v.w));
    }
    for (size_t i = idx; i < NW2 / 4; i += stride) {
        float4 v = ((const float4*)w2)[i];
        ((uint2*)g_woh)[i] = make_uint2(pack_h2(v.x, v.y), pack_h2(v.z, v.w));
    }
}

// ---------------------------------------------------------------------------
// fp16 GEMM, cp.async staging, 64x64 warp tiles.
// C[M,Nc] = A[M,K] @ B[K,Nc]; fp16 operands in gmem. Block 128x128, BK=32,
// 128 threads = 4 warps (2m x 2n). Per k16: 4 LDSM(A) + 4 LDSM.T(B) + 32 MMA.
// mode 0: A=g_xh,  B=g_wqh, C=g_qkvh (fp16; QK_SCALE folded for col0<DI)
// mode 1: A=g_atth,B=g_woh, C=Cp (fp32 out)
// ---------------------------------------------------------------------------
#define SA 40
#define SB 136
#define ABUF_B (128 * SA * 2)        // 10240
#define BBUF_B (32 * SB * 2)         // 8704
#define GEMM_SMEM_BYTES (2 * ABUF_B + 2 * BBUF_B)   // 37888

__global__ __launch_bounds__(128, 2) void gemm_fp16(float* __restrict__ Cp,
                                                    int M, int Nc, int K, int mode)
{
    const __half* A  = (mode == 0) ? g_xh  : g_atth;
    const __half* Bh = (mode == 0) ? g_wqh : g_woh;

    extern __shared__ char dsm[];
    const uint32_t sbase = (uint32_t)__cvta_generic_to_shared(dsm);

    const int tid  = threadIdx.x;
    const int row0 = blockIdx.y * 128;
    const int col0 = blockIdx.x * 128;
    const int wid  = tid >> 5;
    const int lane = tid & 31;
    const int g    = lane >> 2;
    const int tg   = lane & 3;
    const int wm   = (wid & 1) * 64;     // warp row offset
    const int wn   = (wid >> 1) * 64;    // warp col offset
    const int qd   = lane >> 3;
    const int rr   = lane & 7;

    const uint32_t a_off0 = (uint32_t)(((wm + (qd & 1) * 8 + rr) * SA + (qd >> 1) * 8) * 2);
    const uint32_t b_off0 = (uint32_t)((((qd & 1) * 8 + rr) * SB + wn + (qd >> 1) * 8) * 2);

    float acc[4][8][4];
#pragma unroll
    for (int mi = 0; mi < 4; mi++)
#pragma unroll
        for (int ni = 0; ni < 8; ni++)
#pragma unroll
            for (int r = 0; r < 4; r++) acc[mi][ni][r] = 0.f;

    // cp.async seg mapping (128 threads, 4 segs each for A and B):
    // A: 512 segs of 16B (8 halves): seg -> row=seg>>2, col8=(seg&3)*8
    // B: 512 segs: seg -> row=seg>>4, col8=(seg&15)*8
    uint32_t dA[4], dB[4];
    const __half* sAg[4];
    const __half* sBg[4];
#pragma unroll
    for (int j = 0; j < 4; j++) {
        int sa = tid + 128 * j;
        int ar = sa >> 2, ac = (sa & 3) * 8;
        dA[j]  = sbase + (ar * SA + ac) * 2;
        sAg[j] = A + (size_t)(row0 + ar) * K + ac;
        int sb = tid + 128 * j;
        int br = sb >> 4, bc = (sb & 15) * 8;
        dB[j]  = sbase + 2 * ABUF_B + (br * SB + bc) * 2;
        sBg[j] = Bh + (size_t)br * Nc + col0 + bc;
    }

    auto issue_loads = [&](int kt, int buf) {
#pragma unroll
        for (int j = 0; j < 4; j++) {
            cp16(dA[j] + buf * ABUF_B, sAg[j] + kt);
            cp16(dB[j] + buf * BBUF_B, sBg[j] + (size_t)kt * Nc);
        }
        CP_COMMIT();
    };

    auto compute = [&](int buf) {
        const uint32_t ab = sbase + buf * ABUF_B + a_off0;
        const uint32_t bb = sbase + 2 * ABUF_B + buf * BBUF_B + b_off0;
#pragma unroll
        for (int ks = 0; ks < 2; ks++) {
            uint32_t bf[8][2];
#pragma unroll
            for (int pr = 0; pr < 4; pr++) {
                uint32_t t[4];
                ldsm4t(t, bb + ks * (16 * SB * 2) + pr * 32);
                bf[2 * pr    ][0] = t[0]; bf[2 * pr    ][1] = t[1];
                bf[2 * pr + 1][0] = t[2]; bf[2 * pr + 1][1] = t[3];
            }
#pragma unroll
            for (int mi = 0; mi < 4; mi++) {
                uint32_t af[4];
                ldsm4(af, ab + mi * (16 * SA * 2) + ks * 32);
#pragma unroll
                for (int ni = 0; ni < 8; ni++)
                    mma_fp16(acc[mi][ni], af, bf[ni][0], bf[ni][1]);
            }
        }
    };

    issue_loads(0, 0);

    int buf = 0;
    for (int kt = 0; kt < K; kt += 32) {
        CP_WAIT0();
        __syncthreads();
        if (kt + 32 < K) issue_loads(kt + 32, buf ^ 1);
        compute(buf);
        buf ^= 1;
    }

    // Epilogue
    if (mode == 0) {
        const float sc = (col0 < DI) ? QK_SCALE : 1.0f;   // fold Q scaling
        __half* C = g_qkvh;
#pragma unroll
        for (int mi = 0; mi < 4; mi++) {
#pragma unroll
            for (int ni = 0; ni < 8; ni++) {
                const int row = row0 + wm + mi * 16;
                const int col = col0 + wn + ni * 8 + 2 * tg;
                *(uint32_t*)&C[(size_t)(row + g    ) * Nc + col] =
                    pack_h2(acc[mi][ni][0] * sc, acc[mi][ni][1] * sc);
                *(uint32_t*)&C[(size_t)(row + g + 8) * Nc + col] =
                    pack_h2(acc[mi][ni][2] * sc, acc[mi][ni][3] * sc);
            }
        }
    } else {
#pragma unroll
        for (int mi = 0; mi < 4; mi++) {
#pragma unroll
            for (int ni = 0; ni < 8; ni++) {
                const int row = row0 + wm + mi * 16;
                const int col = col0 + wn + ni * 8 + 2 * tg;
                *(float2*)&Cp[(size_t)(row + g    ) * Nc + col] =
                    make_float2(acc[mi][ni][0], acc[mi][ni][1]);
                *(float2*)&Cp[(size_t)(row + g + 8) * Nc + col] =
                    make_float2(acc[mi][ni][2], acc[mi][ni][3]);
            }
        }
    }
}

// ---------------------------------------------------------------------------
// Flash attention (causal): fp16 in/out, fp16 mma, hybrid MUFU/poly exp.
// (unchanged from Round 15 — ~230 us)
// ---------------------------------------------------------------------------
#define SQ  136
#define SP  72
#define QH_B 0
#define KH_B (64 * SQ * 2)
#define VH_B (2 * 64 * SQ * 2)
#define PH_B (3 * 64 * SQ * 2)
#define ATT_SMEM_BYTES (3 * 64 * SQ * 2 + 64 * SP * 2)   // 61440

__global__ __launch_bounds__(128, 3) void attn_mma()
{
    extern __shared__ char dsm[];
    const uint32_t sbase = (uint32_t)__cvta_generic_to_shared(dsm);

    const int bh  = blockIdx.y;
    const int b   = bh >> 4;
    const int h   = bh & 15;
    const int m0  = blockIdx.x * 64;
    const int tid = threadIdx.x;
    const int wid = tid >> 5;
    const int lane = tid & 31;
    const int g   = lane >> 2;
    const int tg  = lane & 3;
    const int qd  = lane >> 3;
    const int rr  = lane & 7;

    const int r0  = wid * 16 + g;
    const int r1  = r0 + 8;
    const int gr0 = m0 + r0;
    const int gr1 = m0 + r1;

    const uint32_t qa_base = sbase + QH_B +
        ((wid * 16 + (qd & 1) * 8 + rr) * SQ + (qd >> 1) * 8) * 2;
    const uint32_t kb_base = sbase + KH_B +
        (((qd >> 1) * 8 + rr) * SQ + (qd & 1) * 8) * 2;
    const uint32_t vb_base = sbase + VH_B +
        (((qd & 1) * 8 + rr) * SQ + (qd >> 1) * 8) * 2;
    const uint32_t pa_base = sbase + PH_B +
        ((wid * 16 + (qd & 1) * 8 + rr) * SP + (qd >> 1) * 8) * 2;

    // ---- Load Q [64 x 128] fp16 verbatim (already scaled) ----
    const __half* Qg = g_qkvh + ((size_t)(b * NN + m0)) * TDI + h * DD;
#pragma unroll
    for (int l = 0; l < 8; l++) {
        int fl = tid + l * 128;
        int r  = fl >> 4;
        int d8 = (fl & 15) * 8;
        *(uint4*)(dsm + QH_B + (r * SQ + d8) * 2) =
            *(const uint4*)(Qg + (size_t)r * TDI + d8);
    }

    float m_r[2] = {-1e30f, -1e30f};
    float l_r[2] = {0.f, 0.f};
    float O[16][4];
#pragma unroll
    for (int ni = 0; ni < 16; ni++)
#pragma unroll
        for (int r = 0; r < 4; r++) O[ni][r] = 0.f;

    const int ntiles = blockIdx.x + 1;
    for (int t = 0; t < ntiles; t++) {
        const int k0 = t * 64;
        __syncthreads();

        const __half* Kg = g_qkvh + ((size_t)(b * NN + k0)) * TDI + DI + h * DD;
        const __half* Vg = Kg + DI;
#pragma unroll
        for (int l = 0; l < 8; l++) {
            int fl = tid + l * 128;
            int r  = fl >> 4;
            int d8 = (fl & 15) * 8;
            *(uint4*)(dsm + KH_B + (r * SQ + d8) * 2) =
                *(const uint4*)(Kg + (size_t)r * TDI + d8);
            *(uint4*)(dsm + VH_B + (r * SQ + d8) * 2) =
                *(const uint4*)(Vg + (size_t)r * TDI + d8);
        }
        __syncthreads();

        // ---- S = Q @ K^T ----
        float S[8][4];
#pragma unroll
        for (int ni = 0; ni < 8; ni++)
#pragma unroll
            for (int r = 0; r < 4; r++) S[ni][r] = 0.f;

#pragma unroll
        for (int ks = 0; ks < 8; ks++) {
            uint32_t af[4];
            ldsm4(af, qa_base + ks * 32);
#pragma unroll
            for (int pr = 0; pr < 4; pr++) {
                uint32_t bt[4];
                ldsm4(bt, kb_base + pr * (16 * SQ * 2) + ks * 32);
                mma_fp16(S[2 * pr    ], af, bt[0], bt[1]);
                mma_fp16(S[2 * pr + 1], af, bt[2], bt[3]);
            }
        }

        if (t == ntiles - 1) {
#pragma unroll
            for (int ni = 0; ni < 8; ni++) {
                const int c = k0 + ni * 8 + 2 * tg;
                if (c     > gr0) S[ni][0] = -1e30f;
                if (c + 1 > gr0) S[ni][1] = -1e30f;
                if (c     > gr1) S[ni][2] = -1e30f;
                if (c + 1 > gr1) S[ni][3] = -1e30f;
            }
        }

        // ---- Softmax (hybrid exp) ----
        float mx0 = -1e30f, mx1 = -1e30f;
#pragma unroll
        for (int ni = 0; ni < 8; ni++) {
            mx0 = fmaxf(mx0, fmaxf(S[ni][0], S[ni][1]));
            mx1 = fmaxf(mx1, fmaxf(S[ni][2], S[ni][3]));
        }
        mx0 = fmaxf(mx0, __shfl_xor_sync(0xffffffffu, mx0, 1));
        mx0 = fmaxf(mx0, __shfl_xor_sync(0xffffffffu, mx0, 2));
        mx1 = fmaxf(mx1, __shfl_xor_sync(0xffffffffu, mx1, 1));
        mx1 = fmaxf(mx1, __shfl_xor_sync(0xffffffffu, mx1, 2));

        const float mn0 = fmaxf(m_r[0], mx0);
        const float mn1 = fmaxf(m_r[1], mx1);
        const float sc0 = __expf(m_r[0] - mn0);
        const float sc1 = __expf(m_r[1] - mn1);

        float sum0 = 0.f, sum1 = 0.f;
        char* p0 = dsm + PH_B + (r0 * SP + 2 * tg) * 2;
        char* p1 = dsm + PH_B + (r1 * SP + 2 * tg) * 2;
#pragma unroll
        for (int ni = 0; ni < 8; ni++) {
            float p00, p01, p10, p11;
            if (ni & 1) {
                p00 = fexp_poly(S[ni][0] - mn0);
                p01 = fexp_poly(S[ni][1] - mn0);
                p10 = fexp_poly(S[ni][2] - mn1);
                p11 = fexp_poly(S[ni][3] - mn1);
            } else {
                p00 = __expf(S[ni][0] - mn0);
                p01 = __expf(S[ni][1] - mn0);
                p10 = __expf(S[ni][2] - mn1);
                p11 = __expf(S[ni][3] - mn1);
            }
            sum0 += p00 + p01;
            sum1 += p10 + p11;
            *(uint32_t*)(p0 + ni * 16) = pack_h2(p00, p01);
            *(uint32_t*)(p1 + ni * 16) = pack_h2(p10, p11);
        }
        sum0 += __shfl_xor_sync(0xffffffffu, sum0, 1);
        sum0 += __shfl_xor_sync(0xffffffffu, sum0, 2);
        sum1 += __shfl_xor_sync(0xffffffffu, sum1, 1);
        sum1 += __shfl_xor_sync(0xffffffffu, sum1, 2);

        l_r[0] = l_r[0] * sc0 + sum0;  m_r[0] = mn0;
        l_r[1] = l_r[1] * sc1 + sum1;  m_r[1] = mn1;

#pragma unroll
        for (int ni = 0; ni < 16; ni++) {
            O[ni][0] *= sc0; O[ni][1] *= sc0;
            O[ni][2] *= sc1; O[ni][3] *= sc1;
        }
        __syncwarp();

        // ---- O += P @ V ----
#pragma unroll
        for (int ks = 0; ks < 4; ks++) {
            uint32_t af[4];
            ldsm4(af, pa_base + ks * 32);
#pragma unroll
            for (int pr = 0; pr < 8; pr++) {
                uint32_t bt[4];
                ldsm4t(bt, vb_base + pr * 32 + ks * (16 * SQ * 2));
                mma_fp16(O[2 * pr    ], af, bt[0], bt[1]);
                mma_fp16(O[2 * pr + 1], af, bt[2], bt[3]);
            }
        }
    }

    // ---- Epilogue: normalize, write fp16 ----
    const float inv0 = 1.0f / l_r[0];
    const float inv1 = 1.0f / l_r[1];
    __half* O0 = g_atth + ((size_t)(b * NN + gr0)) * DI + h * DD;
    __half* O1 = g_atth + ((size_t)(b * NN + gr1)) * DI + h * DD;
#pragma unroll
    for (int ni = 0; ni < 16; ni++) {
        const int c = ni * 8 + 2 * tg;
        *(uint32_t*)&O0[c] = pack_h2(O[ni][0] * inv0, O[ni][1] * inv0);
        *(uint32_t*)&O1[c] = pack_h2(O[ni][2] * inv1, O[ni][3] * inv1);
    }
}

// ---------------------------------------------------------------------------
// Launch
// ---------------------------------------------------------------------------
extern "C" void kernel_launch(void* const* d_in, const int* in_sizes, int n_in,
                              void* d_out, int out_size)
{
    const float* x     = (const float*)d_in[0];   // [2, 2048, 2048]
    const float* w_qkv = (const float*)d_in[1];   // [2048, 6144]
    const float* w_out = (const float*)d_in[2];   // [2048, 2048]
    float* out = (float*)d_out;                   // [2, 2048, 2048]

    cudaFuncSetAttribute(gemm_fp16,
                         cudaFuncAttributeMaxDynamicSharedMemorySize,
                         GEMM_SMEM_BYTES);
    cudaFuncSetAttribute(attn_mma,
                         cudaFuncAttributeMaxDynamicSharedMemorySize,
                         ATT_SMEM_BYTES);

    // 0) fp32 -> fp16 conversion of inputs
    convert_fp16<<<592, 256>>>(x, w_qkv, w_out);

    // 1) QKV projection -> g_qkvh (fp16, Q pre-scaled)
    gemm_fp16<<<dim3(TDI / 128, (BB * NN) / 128), 128, GEMM_SMEM_BYTES>>>(
        nullptr, BB * NN, TDI, DIMM, 0);

    // 2) Causal flash attention: g_qkvh -> g_atth
    attn_mma<<<dim3(NN / 64, BB * HH), 128, ATT_SMEM_BYTES>>>();

    // 3) Output projection: g_atth @ g_woh -> out (fp32)
    gemm_fp16<<<dim3(DIMM / 128, (BB * NN) / 128), 128, GEMM_SMEM_BYTES>>>(
        out, BB * NN, DIMM, DIMM, 1);
}